// round 4
// baseline (speedup 1.0000x reference)
#include <cuda_runtime.h>
#include <cuda_fp16.h>
#include <math.h>
#include <stdint.h>

// Problem constants (fixed shapes)
#define NN   100000
#define MAXE 1600000
#define HID  128
#define NFT  8
#define KTOT 136          // HID + NFT = 17 * 8
#define KPAD 137          // smem row stride (floats)

// ---------------- static device scratch (zero-initialized at load) ----------
__device__ int    g_deg[NN];        // invariant: all-zero at kernel_launch entry
__device__ int    g_off[NN + 1];
__device__ int    g_pos[NN];
__device__ float  g_dinv[NN];
__device__ int    g_srcs[MAXE];
__device__ int    g_part[512];
__device__ __half g_ywA[(size_t)NN * HID];  // fp16 messages layer1 (25.6MB)
__device__ __half g_ywB[(size_t)NN * HID];  // fp16 messages layer2 (25.6MB)
__device__ int    g_is64;

// ---------------- hist (+inline int64/int32 detection) ----------------------
// int64 little-endian: odd 32-bit words are high halves == 0 (ids < 2^17).
__global__ void hist_kernel(const int* __restrict__ ew, int E) {
    __shared__ int s_bad;
    if (threadIdx.x == 0) s_bad = 0;
    __syncthreads();
    if (threadIdx.x < 128 && ew[2 * threadIdx.x + 1] != 0) atomicOr(&s_bad, 1);
    __syncthreads();
    int is64 = s_bad ? 0 : 1;
    if (blockIdx.x == 0 && threadIdx.x == 0) g_is64 = is64;   // for fill
    int e = blockIdx.x * blockDim.x + threadIdx.x;
    if (e >= E) return;
    int d;
    if (is64) { int4 v = ((const int4*)ew)[e]; d = v.z; }
    else      { int2 v = ((const int2*)ew)[e]; d = v.y; }
    atomicAdd(&g_deg[d], 1);
}

// ---------------- hierarchical scan (1024 elems / 256-thread block) ---------
__device__ __forceinline__ int block_scan_excl(int v, int t, int* tot) {
    int lane = t & 31, wid = t >> 5;
    int x = v;
#pragma unroll
    for (int o = 1; o < 32; o <<= 1) {
        int y = __shfl_up_sync(0xffffffffu, x, o);
        if (lane >= o) x += y;
    }
    __shared__ int wsum[8];
    if (lane == 31) wsum[wid] = x;
    __syncthreads();
    int add = 0, total = 0;
#pragma unroll
    for (int w = 0; w < 8; w++) {
        if (w < wid) add += wsum[w];
        total += wsum[w];
    }
    *tot = total;
    __syncthreads();
    return add + x - v;   // exclusive prefix within block
}

__global__ void scan_part_kernel(int n) {
    int t = threadIdx.x, b = blockIdx.x;
    int base = b * 1024 + t * 4;
    int s = 0;
#pragma unroll
    for (int i = 0; i < 4; i++) {
        int idx = base + i;
        if (idx < n) s += g_deg[idx];
    }
    int tot;
    block_scan_excl(s, t, &tot);
    if (t == 0) g_part[b] = tot;
}

// scan_fin: inline top-level scan of partials + per-element scan + init
// pos/dinv + self-zero g_deg (restores the entry invariant for replays).
__global__ void scan_fin_kernel(int nb, int n) {
    __shared__ int sTop[256];
    int t = threadIdx.x, b = blockIdx.x;
    {
        int v = (t < nb) ? g_part[t] : 0;
        int tot;
        int e = block_scan_excl(v, t, &tot);
        sTop[t] = e;
        if (b == 0 && t == 0) g_off[n] = tot;
    }
    __syncthreads();
    int base = b * 1024 + t * 4;
    int d[4];
    int s = 0;
#pragma unroll
    for (int i = 0; i < 4; i++) {
        int idx = base + i;
        d[i] = (idx < n) ? g_deg[idx] : 0;
        s += d[i];
    }
    int tot;
    int e = block_scan_excl(s, t, &tot);
    int run = sTop[b] + e;
#pragma unroll
    for (int i = 0; i < 4; i++) {
        int idx = base + i;
        if (idx < n) {
            g_off[idx] = run;
            g_pos[idx] = run;
            g_dinv[idx] = rsqrtf((float)(d[i] + 1));   // +1 self-loop
            g_deg[idx] = 0;                            // restore invariant
            run += d[i];
        }
    }
}

__global__ void fill_kernel(const int* __restrict__ ew, int E) {
    int e = blockIdx.x * blockDim.x + threadIdx.x;
    if (e >= E) return;
    int s, d;
    if (g_is64) { int4 v = ((const int4*)ew)[e]; s = v.x; d = v.z; }
    else        { int2 v = ((const int2*)ew)[e]; s = v.x; d = v.y; }
    int idx = atomicAdd(&g_pos[d], 1);
    g_srcs[idx] = s;
}

// ---------------- layer-1 matmul (K=8, scalar), fp16 out --------------------
__global__ void mm1_kernel(const float* __restrict__ X, const float* __restrict__ W,
                           __half* __restrict__ out, int n) {
    __shared__ float sW[NFT * HID];
    __shared__ float sIn[64][NFT];
    int t = threadIdx.x, n0 = blockIdx.x * 64;
    for (int i = t; i < NFT * HID; i += 256) sW[i] = W[i];
    for (int i = t; i < 64 * NFT; i += 256) {
        int r = i >> 3, c = i & 7;
        int node = n0 + r;
        sIn[r][c] = (node < n) ? X[(size_t)node * NFT + c] : 0.f;
    }
    __syncthreads();
    int og = t & 15, ng = t >> 4;
    float acc[4][8];
#pragma unroll
    for (int i = 0; i < 4; i++)
#pragma unroll
        for (int j = 0; j < 8; j++) acc[i][j] = 0.f;
    const float4* sW4 = (const float4*)sW;
#pragma unroll
    for (int k = 0; k < NFT; k++) {
        float4 w0 = sW4[k * 32 + og * 2];
        float4 w1 = sW4[k * 32 + og * 2 + 1];
#pragma unroll
        for (int i = 0; i < 4; i++) {
            float a = sIn[ng * 4 + i][k];
            acc[i][0] = fmaf(a, w0.x, acc[i][0]);
            acc[i][1] = fmaf(a, w0.y, acc[i][1]);
            acc[i][2] = fmaf(a, w0.z, acc[i][2]);
            acc[i][3] = fmaf(a, w0.w, acc[i][3]);
            acc[i][4] = fmaf(a, w1.x, acc[i][4]);
            acc[i][5] = fmaf(a, w1.y, acc[i][5]);
            acc[i][6] = fmaf(a, w1.z, acc[i][6]);
            acc[i][7] = fmaf(a, w1.w, acc[i][7]);
        }
    }
#pragma unroll
    for (int i = 0; i < 4; i++) {
        int node = n0 + ng * 4 + i;
        if (node < n) {
            float di = g_dinv[node];
            __half2* o = (__half2*)&out[(size_t)node * HID + og * 8];
            o[0] = __floats2half2_rn(acc[i][0] * di, acc[i][1] * di);
            o[1] = __floats2half2_rn(acc[i][2] * di, acc[i][3] * di);
            o[2] = __floats2half2_rn(acc[i][4] * di, acc[i][5] * di);
            o[3] = __floats2half2_rn(acc[i][6] * di, acc[i][7] * di);
        }
    }
}

// ---------------- TF32 mma machinery (m16n8k8) ------------------------------
__device__ __forceinline__ uint32_t f2tf(float x) {
    uint32_t r;
    asm("cvt.rna.tf32.f32 %0, %1;" : "=r"(r) : "f"(x));
    return r;
}

__device__ __forceinline__ void mma_tf32(float* c, const uint32_t* a, const uint32_t* b) {
    asm volatile(
        "mma.sync.aligned.m16n8k8.row.col.f32.tf32.tf32.f32 "
        "{%0,%1,%2,%3},{%4,%5,%6,%7},{%8,%9},{%0,%1,%2,%3};"
        : "+f"(c[0]), "+f"(c[1]), "+f"(c[2]), "+f"(c[3])
        : "r"(a[0]), "r"(a[1]), "r"(a[2]), "r"(a[3]), "r"(b[0]), "r"(b[1]));
}

// Gather h-rows for this 256-row tile straight into the tf32 smem operand:
// h[node] = relu(dinv[node]*(yw[node] + sum_{s in N(node)} yw[s]) + bias),
// written at column offset HOFF. 512 threads = 16 warps, 16 rows per warp.
template <int HOFF>
__device__ __forceinline__ void gather_to_smem(float* sIn,
                                               const __half* __restrict__ yw,
                                               const float* __restrict__ bias,
                                               int n0, int n, int t) {
    int warp = t >> 5, lane = t & 31;
    int hh = lane >> 4;                     // which edge of the pair
    int fl = lane & 15;                     // 16B feature chunk (8 halves)
    const uint4* yw4 = (const uint4*)yw;
    float bl[8];
#pragma unroll
    for (int j = 0; j < 8; j++) bl[j] = bias[fl * 8 + j];

    for (int r = warp; r < 256; r += 16) {
        int node = n0 + r;
        if (node >= n) {
            if (hh == 0)
#pragma unroll
                for (int j = 0; j < 8; j++) sIn[r * KPAD + HOFF + fl * 8 + j] = 0.f;
            continue;
        }
        float acc[8];
#pragma unroll
        for (int j = 0; j < 8; j++) acc[j] = 0.f;
        if (hh == 0) {                      // self-loop term counted once
            uint4 v = yw4[(size_t)node * 16 + fl];
            float2 a = __half22float2(*(__half2*)&v.x);
            float2 b = __half22float2(*(__half2*)&v.y);
            float2 c = __half22float2(*(__half2*)&v.z);
            float2 d = __half22float2(*(__half2*)&v.w);
            acc[0] = a.x; acc[1] = a.y; acc[2] = b.x; acc[3] = b.y;
            acc[4] = c.x; acc[5] = c.y; acc[6] = d.x; acc[7] = d.y;
        }
        int beg = g_off[node], end = g_off[node + 1];
        for (int base = beg; base < end; base += 32) {
            int idx = base + lane;
            int sreg = (idx < end) ? g_srcs[idx] : 0;
            int m = min(32, end - base);
#pragma unroll 4
            for (int i2 = 0; i2 < m; i2 += 2) {
                int e = i2 + hh;
                int s = __shfl_sync(0xffffffffu, sreg, e);
                if (e < m) {
                    uint4 v = __ldg(&yw4[(size_t)s * 16 + fl]);
                    float2 a = __half22float2(*(__half2*)&v.x);
                    float2 b = __half22float2(*(__half2*)&v.y);
                    float2 c = __half22float2(*(__half2*)&v.z);
                    float2 d = __half22float2(*(__half2*)&v.w);
                    acc[0] += a.x; acc[1] += a.y; acc[2] += b.x; acc[3] += b.y;
                    acc[4] += c.x; acc[5] += c.y; acc[6] += d.x; acc[7] += d.y;
                }
            }
        }
#pragma unroll
        for (int j = 0; j < 8; j++)
            acc[j] += __shfl_xor_sync(0xffffffffu, acc[j], 16);
        if (hh == 0) {
            float di = g_dinv[node];
#pragma unroll
            for (int j = 0; j < 8; j++) {
                float hv = fmaxf(fmaf(di, acc[j], bl[j]), 0.f);
                sIn[r * KPAD + HOFF + fl * 8 + j] = __uint_as_float(f2tf(hv));
            }
        }
    }
}

// X features into sIn at XOFF, W^T into sWt (both tf32).
template <int XOFF>
__device__ __forceinline__ void load_x_w(float* sIn, float* sWt,
                                         const float* __restrict__ X,
                                         const float* __restrict__ W,
                                         int n0, int n, int t) {
    for (int i = t; i < 256 * NFT; i += 512) {
        int r = i >> 3, c = i & 7;
        int node = n0 + r;
        float v = (node < n) ? X[(size_t)node * NFT + c] : 0.f;
        sIn[r * KPAD + XOFF + c] = __uint_as_float(f2tf(v));
    }
    for (int i = t; i < KTOT * HID; i += 512) {
        int k = i >> 7, c = i & 127;           // W row-major [K][128]
        sWt[c * KPAD + k] = __uint_as_float(f2tf(W[i]));
    }
}

// Per-warp mainloop: 32 rows x 64 cols, K=136 in 17 chunks of 8.
__device__ __forceinline__ void mma_main(const float* sIn, const float* sWt,
                                         int rg, int cg, int lr, int lc,
                                         float acc[2][8][4]) {
    for (int kc = 0; kc < 17; kc++) {
        int k0 = kc * 8;
        uint32_t bfr[8][2];
#pragma unroll
        for (int g = 0; g < 8; g++) {
            int col = cg * 64 + g * 8 + lr;
            bfr[g][0] = __float_as_uint(sWt[col * KPAD + k0 + lc]);
            bfr[g][1] = __float_as_uint(sWt[col * KPAD + k0 + 4 + lc]);
        }
        uint32_t afr[2][4];
#pragma unroll
        for (int mt = 0; mt < 2; mt++) {
            int row = rg * 32 + mt * 16;
            afr[mt][0] = __float_as_uint(sIn[(row + lr) * KPAD + k0 + lc]);
            afr[mt][1] = __float_as_uint(sIn[(row + 8 + lr) * KPAD + k0 + lc]);
            afr[mt][2] = __float_as_uint(sIn[(row + lr) * KPAD + k0 + 4 + lc]);
            afr[mt][3] = __float_as_uint(sIn[(row + 8 + lr) * KPAD + k0 + 4 + lc]);
        }
#pragma unroll
        for (int mt = 0; mt < 2; mt++)
#pragma unroll
            for (int g = 0; g < 8; g++)
                mma_tf32(acc[mt][g], afr[mt], bfr[g]);
    }
}

// fused GCN layer 2: h1 = gather(yw1) in smem; yw2 = dinv*([h1|x] @ c2W) fp16.
// Reads yw1 (g_ywA), writes yw2 (g_ywB) — distinct buffers, no hazard.
__global__ void __launch_bounds__(512, 1)
fused_gcn2_kernel(const float* __restrict__ X, const __half* __restrict__ yw1,
                  const float* __restrict__ gbias, const float* __restrict__ W,
                  __half* __restrict__ out, int n) {
    extern __shared__ float sm[];
    float* sIn = sm;
    float* sWt = sm + 256 * KPAD;
    int t = threadIdx.x, n0 = blockIdx.x * 256;
    load_x_w<HID>(sIn, sWt, X, W, n0, n, t);        // layout [h1 | x]
    gather_to_smem<0>(sIn, yw1, gbias, n0, n, t);
    __syncthreads();
    int warp = t >> 5, lane = t & 31;
    int rg = warp >> 1, cg = warp & 1, lr = lane >> 2, lc = lane & 3;
    float acc[2][8][4];
#pragma unroll
    for (int mt = 0; mt < 2; mt++)
#pragma unroll
        for (int g = 0; g < 8; g++)
#pragma unroll
            for (int j = 0; j < 4; j++) acc[mt][g][j] = 0.f;
    mma_main(sIn, sWt, rg, cg, lr, lc, acc);
#pragma unroll
    for (int mt = 0; mt < 2; mt++) {
        int r0 = n0 + rg * 32 + mt * 16 + lr;
        int r1 = r0 + 8;
        float d0 = (r0 < n) ? g_dinv[r0] : 0.f;
        float d1 = (r1 < n) ? g_dinv[r1] : 0.f;
#pragma unroll
        for (int g = 0; g < 8; g++) {
            int col = cg * 64 + g * 8 + 2 * lc;
            if (r0 < n)
                *(__half2*)&out[(size_t)r0 * HID + col] =
                    __floats2half2_rn(acc[mt][g][0] * d0, acc[mt][g][1] * d0);
            if (r1 < n)
                *(__half2*)&out[(size_t)r1 * HID + col] =
                    __floats2half2_rn(acc[mt][g][2] * d1, acc[mt][g][3] * d1);
        }
    }
}

// fused gather + f4 + f5:
// h2 = gather(yw2); out = sigmoid([x | relu([x|h2]@W4+b4)] @ w5 + b5)
__global__ void __launch_bounds__(512, 1)
fused_f45_kernel(const float* __restrict__ X, const __half* __restrict__ yw2,
                 const float* __restrict__ gbias, const float* __restrict__ W,
                 const float* __restrict__ b4, const float* __restrict__ w5,
                 const float* __restrict__ b5, float* __restrict__ out, int n) {
    extern __shared__ float sm[];
    float* sIn = sm;
    float* sWt = sm + 256 * KPAD;
    float* sPart = sWt + 128 * KPAD;     // [256][2]
    int t = threadIdx.x, n0 = blockIdx.x * 256;
    load_x_w<0>(sIn, sWt, X, W, n0, n, t);          // layout [x | h2]
    gather_to_smem<NFT>(sIn, yw2, gbias, n0, n, t);
    __syncthreads();
    int warp = t >> 5, lane = t & 31;
    int rg = warp >> 1, cg = warp & 1, lr = lane >> 2, lc = lane & 3;
    float acc[2][8][4];
#pragma unroll
    for (int mt = 0; mt < 2; mt++)
#pragma unroll
        for (int g = 0; g < 8; g++)
#pragma unroll
            for (int j = 0; j < 4; j++) acc[mt][g][j] = 0.f;
    mma_main(sIn, sWt, rg, cg, lr, lc, acc);

    float b4l[8][2], w5l[8][2];
#pragma unroll
    for (int g = 0; g < 8; g++) {
        int col = cg * 64 + g * 8 + 2 * lc;
        b4l[g][0] = b4[col];         b4l[g][1] = b4[col + 1];
        w5l[g][0] = w5[NFT + col];   w5l[g][1] = w5[NFT + col + 1];
    }
#pragma unroll
    for (int mt = 0; mt < 2; mt++)
#pragma unroll
        for (int h = 0; h < 2; h++) {
            float p = 0.f;
#pragma unroll
            for (int g = 0; g < 8; g++) {
                p = fmaf(fmaxf(acc[mt][g][2 * h] + b4l[g][0], 0.f), w5l[g][0], p);
                p = fmaf(fmaxf(acc[mt][g][2 * h + 1] + b4l[g][1], 0.f), w5l[g][1], p);
            }
            p += __shfl_xor_sync(0xffffffffu, p, 1);
            p += __shfl_xor_sync(0xffffffffu, p, 2);
            if (lc == 0) {
                int rl = rg * 32 + mt * 16 + h * 8 + lr;
                sPart[rl * 2 + cg] = p;
            }
        }
    __syncthreads();
    if (t < 256) {
        int node = n0 + t;
        if (node < n) {
            float s = sPart[t * 2] + sPart[t * 2 + 1] + b5[0];
#pragma unroll
            for (int k = 0; k < NFT; k++) s = fmaf(sIn[t * KPAD + k], w5[k], s);
            out[node] = 1.f / (1.f + expf(-s));
        }
    }
}

// ---------------- launch ----------------------------------------------------
extern "C" void kernel_launch(void* const* d_in, const int* in_sizes, int n_in,
                              void* d_out, int out_size) {
    const float* x   = (const float*)d_in[0];
    const int*   ew  = (const int*)d_in[1];
    const float* c1W = (const float*)d_in[2];
    const float* c1b = (const float*)d_in[3];
    const float* c2W = (const float*)d_in[4];
    const float* c2b = (const float*)d_in[5];
    const float* f4W = (const float*)d_in[18];
    const float* f4b = (const float*)d_in[19];
    const float* f5W = (const float*)d_in[20];
    const float* f5b = (const float*)d_in[21];
    float* out = (float*)d_out;

    const int n = in_sizes[0] / NFT;
    long ewn = in_sizes[1];
    int E = (int)(ewn / 2);
    if (E > MAXE) E = (int)(ewn / 4);

    __half *ywA, *ywB;
    cudaGetSymbolAddress((void**)&ywA, g_ywA);
    cudaGetSymbolAddress((void**)&ywB, g_ywB);

    const int SM_MM  = (256 * KPAD + 128 * KPAD) * 4;        // 210432 B
    const int SM_F45 = SM_MM + 256 * 2 * 4;                  // 212480 B
    cudaFuncSetAttribute(fused_gcn2_kernel,
                         cudaFuncAttributeMaxDynamicSharedMemorySize, SM_MM);
    cudaFuncSetAttribute(fused_f45_kernel,
                         cudaFuncAttributeMaxDynamicSharedMemorySize, SM_F45);

    const int eb256  = (E + 255) / 256;
    const int nb1024 = (n + 1023) / 1024;
    const int mm1b   = (n + 63) / 64;
    const int mmb    = (n + 255) / 256;

    // graph build (g_deg all-zero on entry: BSS init + scan_fin self-zero)
    hist_kernel<<<eb256, 256>>>(ew, E);            // #1 (inline dtype detect)
    scan_part_kernel<<<nb1024, 256>>>(n);          // #2
    scan_fin_kernel<<<nb1024, 256>>>(nb1024, n);   // #3 (inline top scan)
    fill_kernel<<<eb256, 256>>>(ew, E);            // #4  <- ncu capture slot

    // layer 1: yw1 = dinv*(x @ c1W) [fp16]
    mm1_kernel<<<mm1b, 256>>>(x, c1W, ywA, n);     // #5

    // fused layer 2: gather(yw1)->h1 in smem; yw2 = dinv*([h1|x]@c2W) fp16
    fused_gcn2_kernel<<<mmb, 512, SM_MM>>>(x, ywA, c1b, c2W, ywB, n);   // #6

    // fused head: h2 = gather(yw2); out = sigmoid([x|relu([x|h2]@f4W+f4b)]@f5W+f5b)
    fused_f45_kernel<<<mmb, 512, SM_F45>>>(x, ywB, c2b, f4W, f4b, f5W, f5b,
                                           out, n);                     // #7
}

// round 5
// speedup vs baseline: 1.0983x; 1.0983x over previous
#include <cuda_runtime.h>
#include <cuda_fp16.h>
#include <math.h>
#include <stdint.h>

// Problem constants (fixed shapes)
#define NN   100000
#define MAXE 1600000
#define HID  128
#define NFT  8
#define KTOT 136          // HID + NFT = 17 * 8
#define KPAD 137          // smem row stride (floats)

// ---------------- static device scratch (zero-initialized at load) ----------
__device__ int    g_deg[NN];        // invariant: all-zero at kernel_launch entry
__device__ int    g_off[NN + 1];
__device__ int    g_pos[NN];
__device__ float  g_dinv[NN];
__device__ int    g_srcs[MAXE];
__device__ int    g_part[512];
__device__ __half g_yw[(size_t)NN * HID];   // fp16 messages (25.6MB)
__device__ __half g_h[(size_t)NN * HID];    // fp16 hidden   (25.6MB)
__device__ int    g_is64;

// ---------------- hist (+inline int64/int32 detection) ----------------------
// int64 little-endian: odd 32-bit words are high halves == 0 (ids < 2^17).
__global__ void hist_kernel(const int* __restrict__ ew, int E) {
    __shared__ int s_bad;
    if (threadIdx.x == 0) s_bad = 0;
    __syncthreads();
    if (threadIdx.x < 128 && ew[2 * threadIdx.x + 1] != 0) atomicOr(&s_bad, 1);
    __syncthreads();
    int is64 = s_bad ? 0 : 1;
    if (blockIdx.x == 0 && threadIdx.x == 0) g_is64 = is64;   // for fill
    int e = blockIdx.x * blockDim.x + threadIdx.x;
    if (e >= E) return;
    int d;
    if (is64) { int4 v = ((const int4*)ew)[e]; d = v.z; }
    else      { int2 v = ((const int2*)ew)[e]; d = v.y; }
    atomicAdd(&g_deg[d], 1);
}

// ---------------- hierarchical scan (1024 elems / 256-thread block) ---------
__device__ __forceinline__ int block_scan_excl(int v, int t, int* tot) {
    int lane = t & 31, wid = t >> 5;
    int x = v;
#pragma unroll
    for (int o = 1; o < 32; o <<= 1) {
        int y = __shfl_up_sync(0xffffffffu, x, o);
        if (lane >= o) x += y;
    }
    __shared__ int wsum[8];
    if (lane == 31) wsum[wid] = x;
    __syncthreads();
    int add = 0, total = 0;
#pragma unroll
    for (int w = 0; w < 8; w++) {
        if (w < wid) add += wsum[w];
        total += wsum[w];
    }
    *tot = total;
    __syncthreads();
    return add + x - v;   // exclusive prefix within block
}

__global__ void scan_part_kernel(int n) {
    int t = threadIdx.x, b = blockIdx.x;
    int base = b * 1024 + t * 4;
    int s = 0;
#pragma unroll
    for (int i = 0; i < 4; i++) {
        int idx = base + i;
        if (idx < n) s += g_deg[idx];
    }
    int tot;
    block_scan_excl(s, t, &tot);
    if (t == 0) g_part[b] = tot;
}

// scan_fin: inline top-level scan of partials + per-element scan + init
// pos/dinv + self-zero g_deg (restores the entry invariant for replays).
__global__ void scan_fin_kernel(int nb, int n) {
    __shared__ int sTop[256];
    int t = threadIdx.x, b = blockIdx.x;
    {
        int v = (t < nb) ? g_part[t] : 0;
        int tot;
        int e = block_scan_excl(v, t, &tot);
        sTop[t] = e;
        if (b == 0 && t == 0) g_off[n] = tot;
    }
    __syncthreads();
    int base = b * 1024 + t * 4;
    int d[4];
    int s = 0;
#pragma unroll
    for (int i = 0; i < 4; i++) {
        int idx = base + i;
        d[i] = (idx < n) ? g_deg[idx] : 0;
        s += d[i];
    }
    int tot;
    int e = block_scan_excl(s, t, &tot);
    int run = sTop[b] + e;
#pragma unroll
    for (int i = 0; i < 4; i++) {
        int idx = base + i;
        if (idx < n) {
            g_off[idx] = run;
            g_pos[idx] = run;
            g_dinv[idx] = rsqrtf((float)(d[i] + 1));   // +1 self-loop
            g_deg[idx] = 0;                            // restore invariant
            run += d[i];
        }
    }
}

__global__ void fill_kernel(const int* __restrict__ ew, int E) {
    int e = blockIdx.x * blockDim.x + threadIdx.x;
    if (e >= E) return;
    int s, d;
    if (g_is64) { int4 v = ((const int4*)ew)[e]; s = v.x; d = v.z; }
    else        { int2 v = ((const int2*)ew)[e]; s = v.x; d = v.y; }
    int idx = atomicAdd(&g_pos[d], 1);
    g_srcs[idx] = s;
}

// ---------------- layer-1 matmul (K=8, scalar), fp16 out --------------------
__global__ void mm1_kernel(const float* __restrict__ X, const float* __restrict__ W,
                           __half* __restrict__ out, int n) {
    __shared__ float sW[NFT * HID];
    __shared__ float sIn[64][NFT];
    int t = threadIdx.x, n0 = blockIdx.x * 64;
    for (int i = t; i < NFT * HID; i += 256) sW[i] = W[i];
    for (int i = t; i < 64 * NFT; i += 256) {
        int r = i >> 3, c = i & 7;
        int node = n0 + r;
        sIn[r][c] = (node < n) ? X[(size_t)node * NFT + c] : 0.f;
    }
    __syncthreads();
    int og = t & 15, ng = t >> 4;
    float acc[4][8];
#pragma unroll
    for (int i = 0; i < 4; i++)
#pragma unroll
        for (int j = 0; j < 8; j++) acc[i][j] = 0.f;
    const float4* sW4 = (const float4*)sW;
#pragma unroll
    for (int k = 0; k < NFT; k++) {
        float4 w0 = sW4[k * 32 + og * 2];
        float4 w1 = sW4[k * 32 + og * 2 + 1];
#pragma unroll
        for (int i = 0; i < 4; i++) {
            float a = sIn[ng * 4 + i][k];
            acc[i][0] = fmaf(a, w0.x, acc[i][0]);
            acc[i][1] = fmaf(a, w0.y, acc[i][1]);
            acc[i][2] = fmaf(a, w0.z, acc[i][2]);
            acc[i][3] = fmaf(a, w0.w, acc[i][3]);
            acc[i][4] = fmaf(a, w1.x, acc[i][4]);
            acc[i][5] = fmaf(a, w1.y, acc[i][5]);
            acc[i][6] = fmaf(a, w1.z, acc[i][6]);
            acc[i][7] = fmaf(a, w1.w, acc[i][7]);
        }
    }
#pragma unroll
    for (int i = 0; i < 4; i++) {
        int node = n0 + ng * 4 + i;
        if (node < n) {
            float di = g_dinv[node];
            __half2* o = (__half2*)&out[(size_t)node * HID + og * 8];
            o[0] = __floats2half2_rn(acc[i][0] * di, acc[i][1] * di);
            o[1] = __floats2half2_rn(acc[i][2] * di, acc[i][3] * di);
            o[2] = __floats2half2_rn(acc[i][4] * di, acc[i][5] * di);
            o[3] = __floats2half2_rn(acc[i][6] * di, acc[i][7] * di);
        }
    }
}

// ---------------- gather: warp/node, 2 edges/iter, fp16x2 accumulation ------
// h[d] = relu(dinv[d]*(yw[d] + sum_{s in N(d)} yw[s]) + b).
// Per-32-edge-batch partials accumulate in half2 (2 alternating sets to halve
// the dependency chain), flushed to fp32 once per batch.
__global__ void gather_kernel(const __half* __restrict__ yw,
                              const float* __restrict__ bias,
                              __half* __restrict__ out, int n) {
    int gw = (blockIdx.x * blockDim.x + threadIdx.x) >> 5;
    if (gw >= n) return;                    // uniform per warp
    int lane = threadIdx.x & 31;
    int hh = lane >> 4;                     // which edge of the pair
    int fl = lane & 15;                     // 16B feature chunk (8 halves)
    const uint4* yw4 = (const uint4*)yw;

    float acc[8];
#pragma unroll
    for (int j = 0; j < 8; j++) acc[j] = 0.f;

    // self-loop term in fp32 (counted once, by half 0)
    if (hh == 0) {
        uint4 v = yw4[(size_t)gw * 16 + fl];
        float2 a = __half22float2(*(__half2*)&v.x);
        float2 b = __half22float2(*(__half2*)&v.y);
        float2 c = __half22float2(*(__half2*)&v.z);
        float2 d = __half22float2(*(__half2*)&v.w);
        acc[0] = a.x; acc[1] = a.y; acc[2] = b.x; acc[3] = b.y;
        acc[4] = c.x; acc[5] = c.y; acc[6] = d.x; acc[7] = d.y;
    }

    int beg = g_off[gw], end = g_off[gw + 1];
    const __half2 hz = __floats2half2_rn(0.f, 0.f);
    for (int base = beg; base < end; base += 32) {
        int idx = base + lane;
        int sreg = (idx < end) ? g_srcs[idx] : 0;
        int m = min(32, end - base);
        __half2 hacc[2][4];
#pragma unroll
        for (int u = 0; u < 2; u++)
#pragma unroll
            for (int j = 0; j < 4; j++) hacc[u][j] = hz;
#pragma unroll 8
        for (int i2 = 0; i2 < m; i2 += 2) {
            int e = i2 + hh;                              // e <= 31 always
            int s = __shfl_sync(0xffffffffu, sreg, e);
            if (e < m) {
                uint4 v = __ldg(&yw4[(size_t)s * 16 + fl]);
                int u = (i2 >> 1) & 1;
                hacc[u][0] = __hadd2(hacc[u][0], *(__half2*)&v.x);
                hacc[u][1] = __hadd2(hacc[u][1], *(__half2*)&v.y);
                hacc[u][2] = __hadd2(hacc[u][2], *(__half2*)&v.z);
                hacc[u][3] = __hadd2(hacc[u][3], *(__half2*)&v.w);
            }
        }
        // flush batch partials to fp32
#pragma unroll
        for (int j = 0; j < 4; j++) {
            float2 f0 = __half22float2(hacc[0][j]);
            float2 f1 = __half22float2(hacc[1][j]);
            acc[2 * j]     += f0.x + f1.x;
            acc[2 * j + 1] += f0.y + f1.y;
        }
    }

    // combine the two edge-halves (lane l <-> l+16 hold same features)
#pragma unroll
    for (int j = 0; j < 8; j++)
        acc[j] += __shfl_xor_sync(0xffffffffu, acc[j], 16);

    if (hh == 0) {
        float di = g_dinv[gw];
        const float4* b4 = (const float4*)bias;
        float4 ba = b4[fl * 2], bb = b4[fl * 2 + 1];
        float r0 = fmaxf(fmaf(di, acc[0], ba.x), 0.f);
        float r1 = fmaxf(fmaf(di, acc[1], ba.y), 0.f);
        float r2 = fmaxf(fmaf(di, acc[2], ba.z), 0.f);
        float r3 = fmaxf(fmaf(di, acc[3], ba.w), 0.f);
        float r4 = fmaxf(fmaf(di, acc[4], bb.x), 0.f);
        float r5 = fmaxf(fmaf(di, acc[5], bb.y), 0.f);
        float r6 = fmaxf(fmaf(di, acc[6], bb.z), 0.f);
        float r7 = fmaxf(fmaf(di, acc[7], bb.w), 0.f);
        uint4 o;
        *(__half2*)&o.x = __floats2half2_rn(r0, r1);
        *(__half2*)&o.y = __floats2half2_rn(r2, r3);
        *(__half2*)&o.z = __floats2half2_rn(r4, r5);
        *(__half2*)&o.w = __floats2half2_rn(r6, r7);
        ((uint4*)out)[(size_t)gw * 16 + fl] = o;
    }
}

// ---------------- TF32 mma machinery (m16n8k8) ------------------------------
__device__ __forceinline__ uint32_t f2tf(float x) {
    uint32_t r;
    asm("cvt.rna.tf32.f32 %0, %1;" : "=r"(r) : "f"(x));
    return r;
}

__device__ __forceinline__ void mma_tf32(float* c, const uint32_t* a, const uint32_t* b) {
    asm volatile(
        "mma.sync.aligned.m16n8k8.row.col.f32.tf32.tf32.f32 "
        "{%0,%1,%2,%3},{%4,%5,%6,%7},{%8,%9},{%0,%1,%2,%3};"
        : "+f"(c[0]), "+f"(c[1]), "+f"(c[2]), "+f"(c[3])
        : "r"(a[0]), "r"(a[1]), "r"(a[2]), "r"(a[3]), "r"(b[0]), "r"(b[1]));
}

// sIn[256][KPAD] = tf32(concat), sWt[col][k] = tf32(W^T). 512 threads.
// XFIRST: input = [X(8) | H(128)]; else [H(128) | X(8)].
template <bool XFIRST>
__device__ __forceinline__ void load_tiles(float* sIn, float* sWt,
                                           const float* __restrict__ X,
                                           const __half* __restrict__ H,
                                           const float* __restrict__ W,
                                           int n0, int n, int t) {
    int warp = t >> 5, lane = t & 31;
    for (int r = warp; r < 256; r += 16) {
        int node = n0 + r;
        bool ok = node < n;
        for (int c = lane; c < KTOT; c += 32) {
            float v = 0.f;
            if (ok) {
                if (XFIRST) v = (c < NFT) ? X[(size_t)node * NFT + c]
                                          : __half2float(H[(size_t)node * HID + (c - NFT)]);
                else        v = (c < HID) ? __half2float(H[(size_t)node * HID + c])
                                          : X[(size_t)node * NFT + (c - HID)];
            }
            sIn[r * KPAD + c] = __uint_as_float(f2tf(v));
        }
    }
    for (int i = t; i < KTOT * HID; i += 512) {
        int k = i >> 7, c = i & 127;           // W row-major [K][128]
        sWt[c * KPAD + k] = __uint_as_float(f2tf(W[i]));
    }
}

// Per-warp mainloop: 32 rows x 64 cols, K=136 in 17 chunks of 8.
__device__ __forceinline__ void mma_main(const float* sIn, const float* sWt,
                                         int rg, int cg, int lr, int lc,
                                         float acc[2][8][4]) {
    for (int kc = 0; kc < 17; kc++) {
        int k0 = kc * 8;
        uint32_t bfr[8][2];
#pragma unroll
        for (int g = 0; g < 8; g++) {
            int col = cg * 64 + g * 8 + lr;
            bfr[g][0] = __float_as_uint(sWt[col * KPAD + k0 + lc]);
            bfr[g][1] = __float_as_uint(sWt[col * KPAD + k0 + 4 + lc]);
        }
        uint32_t afr[2][4];
#pragma unroll
        for (int mt = 0; mt < 2; mt++) {
            int row = rg * 32 + mt * 16;
            afr[mt][0] = __float_as_uint(sIn[(row + lr) * KPAD + k0 + lc]);
            afr[mt][1] = __float_as_uint(sIn[(row + 8 + lr) * KPAD + k0 + lc]);
            afr[mt][2] = __float_as_uint(sIn[(row + lr) * KPAD + k0 + 4 + lc]);
            afr[mt][3] = __float_as_uint(sIn[(row + 8 + lr) * KPAD + k0 + 4 + lc]);
        }
#pragma unroll
        for (int mt = 0; mt < 2; mt++)
#pragma unroll
            for (int g = 0; g < 8; g++)
                mma_tf32(acc[mt][g], afr[mt], bfr[g]);
    }
}

// yw = dinv * ([H|X] @ W), fp16 out. Tile 256 rows x 128 cols, 512 threads.
__global__ void __launch_bounds__(512, 1)
mm2_tf32_kernel(const float* __restrict__ X, const __half* __restrict__ H,
                const float* __restrict__ W, __half* __restrict__ out, int n) {
    extern __shared__ float sm[];
    float* sIn = sm;
    float* sWt = sm + 256 * KPAD;
    int t = threadIdx.x, n0 = blockIdx.x * 256;
    load_tiles<false>(sIn, sWt, X, H, W, n0, n, t);
    __syncthreads();
    int warp = t >> 5, lane = t & 31;
    int rg = warp >> 1, cg = warp & 1, lr = lane >> 2, lc = lane & 3;
    float acc[2][8][4];
#pragma unroll
    for (int mt = 0; mt < 2; mt++)
#pragma unroll
        for (int g = 0; g < 8; g++)
#pragma unroll
            for (int j = 0; j < 4; j++) acc[mt][g][j] = 0.f;
    mma_main(sIn, sWt, rg, cg, lr, lc, acc);
#pragma unroll
    for (int mt = 0; mt < 2; mt++) {
        int r0 = n0 + rg * 32 + mt * 16 + lr;
        int r1 = r0 + 8;
        float d0 = (r0 < n) ? g_dinv[r0] : 0.f;
        float d1 = (r1 < n) ? g_dinv[r1] : 0.f;
#pragma unroll
        for (int g = 0; g < 8; g++) {
            int col = cg * 64 + g * 8 + 2 * lc;
            if (r0 < n)
                *(__half2*)&out[(size_t)r0 * HID + col] =
                    __floats2half2_rn(acc[mt][g][0] * d0, acc[mt][g][1] * d0);
            if (r1 < n)
                *(__half2*)&out[(size_t)r1 * HID + col] =
                    __floats2half2_rn(acc[mt][g][2] * d1, acc[mt][g][3] * d1);
        }
    }
}

// fused f4+f5: out = sigmoid([x | relu([x|h]@W4+b4)] @ w5 + b5)
__global__ void __launch_bounds__(512, 1)
f45_tf32_kernel(const float* __restrict__ X, const __half* __restrict__ Hin,
                const float* __restrict__ W, const float* __restrict__ b4,
                const float* __restrict__ w5, const float* __restrict__ b5,
                float* __restrict__ out, int n) {
    extern __shared__ float sm[];
    float* sIn = sm;
    float* sWt = sm + 256 * KPAD;
    float* sPart = sWt + 128 * KPAD;     // [256][2]
    int t = threadIdx.x, n0 = blockIdx.x * 256;
    load_tiles<true>(sIn, sWt, X, Hin, W, n0, n, t);
    __syncthreads();
    int warp = t >> 5, lane = t & 31;
    int rg = warp >> 1, cg = warp & 1, lr = lane >> 2, lc = lane & 3;
    float acc[2][8][4];
#pragma unroll
    for (int mt = 0; mt < 2; mt++)
#pragma unroll
        for (int g = 0; g < 8; g++)
#pragma unroll
            for (int j = 0; j < 4; j++) acc[mt][g][j] = 0.f;
    mma_main(sIn, sWt, rg, cg, lr, lc, acc);

    float b4l[8][2], w5l[8][2];
#pragma unroll
    for (int g = 0; g < 8; g++) {
        int col = cg * 64 + g * 8 + 2 * lc;
        b4l[g][0] = b4[col];         b4l[g][1] = b4[col + 1];
        w5l[g][0] = w5[NFT + col];   w5l[g][1] = w5[NFT + col + 1];
    }
#pragma unroll
    for (int mt = 0; mt < 2; mt++)
#pragma unroll
        for (int h = 0; h < 2; h++) {
            float p = 0.f;
#pragma unroll
            for (int g = 0; g < 8; g++) {
                p = fmaf(fmaxf(acc[mt][g][2 * h] + b4l[g][0], 0.f), w5l[g][0], p);
                p = fmaf(fmaxf(acc[mt][g][2 * h + 1] + b4l[g][1], 0.f), w5l[g][1], p);
            }
            p += __shfl_xor_sync(0xffffffffu, p, 1);
            p += __shfl_xor_sync(0xffffffffu, p, 2);
            if (lc == 0) {
                int rl = rg * 32 + mt * 16 + h * 8 + lr;
                sPart[rl * 2 + cg] = p;
            }
        }
    __syncthreads();
    if (t < 256) {
        int node = n0 + t;
        if (node < n) {
            float s = sPart[t * 2] + sPart[t * 2 + 1] + b5[0];
#pragma unroll
            for (int k = 0; k < NFT; k++) s = fmaf(sIn[t * KPAD + k], w5[k], s);
            out[node] = 1.f / (1.f + expf(-s));
        }
    }
}

// ---------------- launch ----------------------------------------------------
extern "C" void kernel_launch(void* const* d_in, const int* in_sizes, int n_in,
                              void* d_out, int out_size) {
    const float* x   = (const float*)d_in[0];
    const int*   ew  = (const int*)d_in[1];
    const float* c1W = (const float*)d_in[2];
    const float* c1b = (const float*)d_in[3];
    const float* c2W = (const float*)d_in[4];
    const float* c2b = (const float*)d_in[5];
    const float* f4W = (const float*)d_in[18];
    const float* f4b = (const float*)d_in[19];
    const float* f5W = (const float*)d_in[20];
    const float* f5b = (const float*)d_in[21];
    float* out = (float*)d_out;

    const int n = in_sizes[0] / NFT;
    long ewn = in_sizes[1];
    int E = (int)(ewn / 2);
    if (E > MAXE) E = (int)(ewn / 4);

    __half *yw, *h;
    cudaGetSymbolAddress((void**)&yw, g_yw);
    cudaGetSymbolAddress((void**)&h, g_h);

    const int SM_MM  = (256 * KPAD + 128 * KPAD) * 4;        // 210432 B
    const int SM_F45 = SM_MM + 256 * 2 * 4;                  // 212480 B
    cudaFuncSetAttribute(mm2_tf32_kernel,
                         cudaFuncAttributeMaxDynamicSharedMemorySize, SM_MM);
    cudaFuncSetAttribute(f45_tf32_kernel,
                         cudaFuncAttributeMaxDynamicSharedMemorySize, SM_F45);

    const int eb256   = (E + 255) / 256;
    const int nb1024  = (n + 1023) / 1024;
    const int mm1b    = (n + 63) / 64;
    const int mmb     = (n + 255) / 256;
    const int gatherb = (n + 7) / 8;     // 8 warps (nodes) per 256-thread block

    // graph build (g_deg all-zero on entry: BSS init + scan_fin self-zero)
    hist_kernel<<<eb256, 256>>>(ew, E);            // #1 (inline dtype detect)
    scan_part_kernel<<<nb1024, 256>>>(n);          // #2
    scan_fin_kernel<<<nb1024, 256>>>(nb1024, n);   // #3 (inline top scan)
    fill_kernel<<<eb256, 256>>>(ew, E);            // #4  <- ncu capture slot

    // layer 1: yw1 = dinv*(x @ c1W) [fp16]; h1 = relu(dinv*(self+sum)+c1b)
    mm1_kernel<<<mm1b, 256>>>(x, c1W, yw, n);      // #5
    gather_kernel<<<gatherb, 256>>>(yw, c1b, h, n);// #6

    // layer 2: yw2 = dinv*([h1|x] @ c2W) [tf32 mma]; h2 = relu(...)
    mm2_tf32_kernel<<<mmb, 512, SM_MM>>>(x, h, c2W, yw, n);   // #7
    gather_kernel<<<gatherb, 256>>>(yw, c2b, h, n);           // #8

    // fused head: out = sigmoid([x | relu([x|h2]@f4W+f4b)] @ f5W + f5b)
    f45_tf32_kernel<<<mmb, 512, SM_F45>>>(x, h, f4W, f4b, f5W, f5b, out, n); // #9
}

// round 6
// speedup vs baseline: 1.4374x; 1.3087x over previous
#include <cuda_runtime.h>
#include <cuda_fp16.h>
#include <math.h>
#include <stdint.h>

// Problem constants (fixed shapes)
#define NN   100000
#define MAXE 1600000
#define HID  128
#define NFT  8
#define KTOT 136          // HID + NFT = 17 * 8
#define KPAD 137          // smem row stride (floats)

// ---------------- static device scratch (zero-initialized at load) ----------
__device__ int    g_deg[NN];        // invariant: all-zero at kernel_launch entry
__device__ int    g_off[NN + 1];
__device__ int    g_pos[NN];
__device__ float  g_dinv[NN];
__device__ int    g_srcs[MAXE];
__device__ int    g_part[512];
__device__ __half g_yw[(size_t)NN * HID];   // fp16 messages (25.6MB)
__device__ __half g_h[(size_t)NN * HID];    // fp16 hidden   (25.6MB)
__device__ int    g_is64;

// ---------------- hist (+inline int64/int32 detection) ----------------------
// int64 little-endian: odd 32-bit words are high halves == 0 (ids < 2^17).
__global__ void hist_kernel(const int* __restrict__ ew, int E) {
    __shared__ int s_bad;
    if (threadIdx.x == 0) s_bad = 0;
    __syncthreads();
    if (threadIdx.x < 128 && ew[2 * threadIdx.x + 1] != 0) atomicOr(&s_bad, 1);
    __syncthreads();
    int is64 = s_bad ? 0 : 1;
    if (blockIdx.x == 0 && threadIdx.x == 0) g_is64 = is64;   // for fill
    int e = blockIdx.x * blockDim.x + threadIdx.x;
    if (e >= E) return;
    int d;
    if (is64) { int4 v = ((const int4*)ew)[e]; d = v.z; }
    else      { int2 v = ((const int2*)ew)[e]; d = v.y; }
    atomicAdd(&g_deg[d], 1);
}

// ---------------- hierarchical scan (1024 elems / 256-thread block) ---------
__device__ __forceinline__ int block_scan_excl(int v, int t, int* tot) {
    int lane = t & 31, wid = t >> 5;
    int x = v;
#pragma unroll
    for (int o = 1; o < 32; o <<= 1) {
        int y = __shfl_up_sync(0xffffffffu, x, o);
        if (lane >= o) x += y;
    }
    __shared__ int wsum[8];
    if (lane == 31) wsum[wid] = x;
    __syncthreads();
    int add = 0, total = 0;
#pragma unroll
    for (int w = 0; w < 8; w++) {
        if (w < wid) add += wsum[w];
        total += wsum[w];
    }
    *tot = total;
    __syncthreads();
    return add + x - v;   // exclusive prefix within block
}

__global__ void scan_part_kernel(int n) {
    int t = threadIdx.x, b = blockIdx.x;
    int base = b * 1024 + t * 4;
    int s = 0;
#pragma unroll
    for (int i = 0; i < 4; i++) {
        int idx = base + i;
        if (idx < n) s += g_deg[idx];
    }
    int tot;
    block_scan_excl(s, t, &tot);
    if (t == 0) g_part[b] = tot;
}

// scan_fin: inline top-level scan of partials + per-element scan + init
// pos/dinv + self-zero g_deg (restores the entry invariant for replays).
__global__ void scan_fin_kernel(int nb, int n) {
    __shared__ int sTop[256];
    int t = threadIdx.x, b = blockIdx.x;
    {
        int v = (t < nb) ? g_part[t] : 0;
        int tot;
        int e = block_scan_excl(v, t, &tot);
        sTop[t] = e;
        if (b == 0 && t == 0) g_off[n] = tot;
    }
    __syncthreads();
    int base = b * 1024 + t * 4;
    int d[4];
    int s = 0;
#pragma unroll
    for (int i = 0; i < 4; i++) {
        int idx = base + i;
        d[i] = (idx < n) ? g_deg[idx] : 0;
        s += d[i];
    }
    int tot;
    int e = block_scan_excl(s, t, &tot);
    int run = sTop[b] + e;
#pragma unroll
    for (int i = 0; i < 4; i++) {
        int idx = base + i;
        if (idx < n) {
            g_off[idx] = run;
            g_pos[idx] = run;
            g_dinv[idx] = rsqrtf((float)(d[i] + 1));   // +1 self-loop
            g_deg[idx] = 0;                            // restore invariant
            run += d[i];
        }
    }
}

__global__ void fill_kernel(const int* __restrict__ ew, int E) {
    int e = blockIdx.x * blockDim.x + threadIdx.x;
    if (e >= E) return;
    int s, d;
    if (g_is64) { int4 v = ((const int4*)ew)[e]; s = v.x; d = v.z; }
    else        { int2 v = ((const int2*)ew)[e]; s = v.x; d = v.y; }
    int idx = atomicAdd(&g_pos[d], 1);
    g_srcs[idx] = s;
}

// ---------------- layer-1 matmul (K=8, scalar), fp16 out --------------------
__global__ void mm1_kernel(const float* __restrict__ X, const float* __restrict__ W,
                           __half* __restrict__ out, int n) {
    __shared__ float sW[NFT * HID];
    __shared__ float sIn[64][NFT];
    int t = threadIdx.x, n0 = blockIdx.x * 64;
    for (int i = t; i < NFT * HID; i += 256) sW[i] = W[i];
    for (int i = t; i < 64 * NFT; i += 256) {
        int r = i >> 3, c = i & 7;
        int node = n0 + r;
        sIn[r][c] = (node < n) ? X[(size_t)node * NFT + c] : 0.f;
    }
    __syncthreads();
    int og = t & 15, ng = t >> 4;
    float acc[4][8];
#pragma unroll
    for (int i = 0; i < 4; i++)
#pragma unroll
        for (int j = 0; j < 8; j++) acc[i][j] = 0.f;
    const float4* sW4 = (const float4*)sW;
#pragma unroll
    for (int k = 0; k < NFT; k++) {
        float4 w0 = sW4[k * 32 + og * 2];
        float4 w1 = sW4[k * 32 + og * 2 + 1];
#pragma unroll
        for (int i = 0; i < 4; i++) {
            float a = sIn[ng * 4 + i][k];
            acc[i][0] = fmaf(a, w0.x, acc[i][0]);
            acc[i][1] = fmaf(a, w0.y, acc[i][1]);
            acc[i][2] = fmaf(a, w0.z, acc[i][2]);
            acc[i][3] = fmaf(a, w0.w, acc[i][3]);
            acc[i][4] = fmaf(a, w1.x, acc[i][4]);
            acc[i][5] = fmaf(a, w1.y, acc[i][5]);
            acc[i][6] = fmaf(a, w1.z, acc[i][6]);
            acc[i][7] = fmaf(a, w1.w, acc[i][7]);
        }
    }
#pragma unroll
    for (int i = 0; i < 4; i++) {
        int node = n0 + ng * 4 + i;
        if (node < n) {
            float di = g_dinv[node];
            __half2* o = (__half2*)&out[(size_t)node * HID + og * 8];
            o[0] = __floats2half2_rn(acc[i][0] * di, acc[i][1] * di);
            o[1] = __floats2half2_rn(acc[i][2] * di, acc[i][3] * di);
            o[2] = __floats2half2_rn(acc[i][4] * di, acc[i][5] * di);
            o[3] = __floats2half2_rn(acc[i][6] * di, acc[i][7] * di);
        }
    }
}

// ---------------- gather: warp/node, 2 edges per iteration (R3 proven) ------
// h[d] = relu(dinv[d]*(yw[d] + sum_{s in N(d)} yw[s]) + b), fp16 in/out,
// fp32 accumulation.
__global__ void gather_kernel(const __half* __restrict__ yw,
                              const float* __restrict__ bias,
                              __half* __restrict__ out, int n) {
    int gw = (blockIdx.x * blockDim.x + threadIdx.x) >> 5;
    if (gw >= n) return;                    // uniform per warp
    int lane = threadIdx.x & 31;
    int hh = lane >> 4;                     // which edge of the pair
    int fl = lane & 15;                     // 16B feature chunk (8 halves)
    const uint4* yw4 = (const uint4*)yw;    // 16 uint4 per 128-half row

    float acc[8];
#pragma unroll
    for (int j = 0; j < 8; j++) acc[j] = 0.f;

    // self-loop term (counted once, by half 0)
    if (hh == 0) {
        uint4 v = yw4[(size_t)gw * 16 + fl];
        float2 a = __half22float2(*(__half2*)&v.x);
        float2 b = __half22float2(*(__half2*)&v.y);
        float2 c = __half22float2(*(__half2*)&v.z);
        float2 d = __half22float2(*(__half2*)&v.w);
        acc[0] = a.x; acc[1] = a.y; acc[2] = b.x; acc[3] = b.y;
        acc[4] = c.x; acc[5] = c.y; acc[6] = d.x; acc[7] = d.y;
    }

    int beg = g_off[gw], end = g_off[gw + 1];
    for (int base = beg; base < end; base += 32) {
        int idx = base + lane;
        int sreg = (idx < end) ? g_srcs[idx] : 0;
        int m = min(32, end - base);
#pragma unroll 4
        for (int i2 = 0; i2 < m; i2 += 2) {
            int e = i2 + hh;                              // e <= 31 always
            int s = __shfl_sync(0xffffffffu, sreg, e);
            if (e < m) {
                uint4 v = __ldg(&yw4[(size_t)s * 16 + fl]);
                float2 a = __half22float2(*(__half2*)&v.x);
                float2 b = __half22float2(*(__half2*)&v.y);
                float2 c = __half22float2(*(__half2*)&v.z);
                float2 d = __half22float2(*(__half2*)&v.w);
                acc[0] += a.x; acc[1] += a.y; acc[2] += b.x; acc[3] += b.y;
                acc[4] += c.x; acc[5] += c.y; acc[6] += d.x; acc[7] += d.y;
            }
        }
    }

    // combine the two edge-halves (lane l <-> l+16 hold same features)
#pragma unroll
    for (int j = 0; j < 8; j++)
        acc[j] += __shfl_xor_sync(0xffffffffu, acc[j], 16);

    if (hh == 0) {
        float di = g_dinv[gw];
        const float4* b4 = (const float4*)bias;
        float4 ba = b4[fl * 2], bb = b4[fl * 2 + 1];
        float r0 = fmaxf(fmaf(di, acc[0], ba.x), 0.f);
        float r1 = fmaxf(fmaf(di, acc[1], ba.y), 0.f);
        float r2 = fmaxf(fmaf(di, acc[2], ba.z), 0.f);
        float r3 = fmaxf(fmaf(di, acc[3], ba.w), 0.f);
        float r4 = fmaxf(fmaf(di, acc[4], bb.x), 0.f);
        float r5 = fmaxf(fmaf(di, acc[5], bb.y), 0.f);
        float r6 = fmaxf(fmaf(di, acc[6], bb.z), 0.f);
        float r7 = fmaxf(fmaf(di, acc[7], bb.w), 0.f);
        uint4 o;
        *(__half2*)&o.x = __floats2half2_rn(r0, r1);
        *(__half2*)&o.y = __floats2half2_rn(r2, r3);
        *(__half2*)&o.z = __floats2half2_rn(r4, r5);
        *(__half2*)&o.w = __floats2half2_rn(r6, r7);
        ((uint4*)out)[(size_t)gw * 16 + fl] = o;
    }
}

// ---------------- TF32 mma machinery (m16n8k8) ------------------------------
__device__ __forceinline__ uint32_t f2tf(float x) {
    uint32_t r;
    asm("cvt.rna.tf32.f32 %0, %1;" : "=r"(r) : "f"(x));
    return r;
}

__device__ __forceinline__ void mma_tf32(float* c, const uint32_t* a, const uint32_t* b) {
    asm volatile(
        "mma.sync.aligned.m16n8k8.row.col.f32.tf32.tf32.f32 "
        "{%0,%1,%2,%3},{%4,%5,%6,%7},{%8,%9},{%0,%1,%2,%3};"
        : "+f"(c[0]), "+f"(c[1]), "+f"(c[2]), "+f"(c[3])
        : "r"(a[0]), "r"(a[1]), "r"(a[2]), "r"(a[3]), "r"(b[0]), "r"(b[1]));
}

// sIn[256][KPAD] = tf32(concat), sWt[col][k] = tf32(W^T). 512 threads.
// H rows are read as one uint4 (16B) per lane: 16 lanes cover the full 256B
// row coalesced; lanes 16-23 read the 8 X features.
// XFIRST: input = [X(8) | H(128)]; else [H(128) | X(8)].
template <bool XFIRST>
__device__ __forceinline__ void load_tiles(float* sIn, float* sWt,
                                           const float* __restrict__ X,
                                           const __half* __restrict__ H,
                                           const float* __restrict__ W,
                                           int n0, int n, int t) {
    int warp = t >> 5, lane = t & 31;
    const int hbase = XFIRST ? NFT : 0;
    const int xbase = XFIRST ? 0 : HID;
    for (int r = warp; r < 256; r += 16) {
        int node = n0 + r;
        bool ok = node < n;
        if (lane < 16) {
            uint4 v = make_uint4(0u, 0u, 0u, 0u);
            if (ok) v = __ldg(((const uint4*)(H + (size_t)node * HID)) + lane);
            float2 a = __half22float2(*(__half2*)&v.x);
            float2 b = __half22float2(*(__half2*)&v.y);
            float2 c = __half22float2(*(__half2*)&v.z);
            float2 d = __half22float2(*(__half2*)&v.w);
            float* p = &sIn[r * KPAD + hbase + lane * 8];
            p[0] = __uint_as_float(f2tf(a.x));
            p[1] = __uint_as_float(f2tf(a.y));
            p[2] = __uint_as_float(f2tf(b.x));
            p[3] = __uint_as_float(f2tf(b.y));
            p[4] = __uint_as_float(f2tf(c.x));
            p[5] = __uint_as_float(f2tf(c.y));
            p[6] = __uint_as_float(f2tf(d.x));
            p[7] = __uint_as_float(f2tf(d.y));
        } else if (lane < 24) {
            int c = lane - 16;
            float xv = ok ? X[(size_t)node * NFT + c] : 0.f;
            sIn[r * KPAD + xbase + c] = __uint_as_float(f2tf(xv));
        }
    }
    for (int i = t; i < KTOT * HID; i += 512) {
        int k = i >> 7, c = i & 127;           // W row-major [K][128]
        sWt[c * KPAD + k] = __uint_as_float(f2tf(W[i]));
    }
}

// Per-warp mainloop: 32 rows x 64 cols, K=136 in 17 chunks of 8.
__device__ __forceinline__ void mma_main(const float* sIn, const float* sWt,
                                         int rg, int cg, int lr, int lc,
                                         float acc[2][8][4]) {
    for (int kc = 0; kc < 17; kc++) {
        int k0 = kc * 8;
        uint32_t bfr[8][2];
#pragma unroll
        for (int g = 0; g < 8; g++) {
            int col = cg * 64 + g * 8 + lr;
            bfr[g][0] = __float_as_uint(sWt[col * KPAD + k0 + lc]);
            bfr[g][1] = __float_as_uint(sWt[col * KPAD + k0 + 4 + lc]);
        }
        uint32_t afr[2][4];
#pragma unroll
        for (int mt = 0; mt < 2; mt++) {
            int row = rg * 32 + mt * 16;
            afr[mt][0] = __float_as_uint(sIn[(row + lr) * KPAD + k0 + lc]);
            afr[mt][1] = __float_as_uint(sIn[(row + 8 + lr) * KPAD + k0 + lc]);
            afr[mt][2] = __float_as_uint(sIn[(row + lr) * KPAD + k0 + 4 + lc]);
            afr[mt][3] = __float_as_uint(sIn[(row + 8 + lr) * KPAD + k0 + 4 + lc]);
        }
#pragma unroll
        for (int mt = 0; mt < 2; mt++)
#pragma unroll
            for (int g = 0; g < 8; g++)
                mma_tf32(acc[mt][g], afr[mt], bfr[g]);
    }
}

// yw = dinv * ([H|X] @ W), fp16 out. Tile 256 rows x 128 cols, 512 threads.
__global__ void __launch_bounds__(512, 1)
mm2_tf32_kernel(const float* __restrict__ X, const __half* __restrict__ H,
                const float* __restrict__ W, __half* __restrict__ out, int n) {
    extern __shared__ float sm[];
    float* sIn = sm;
    float* sWt = sm + 256 * KPAD;
    int t = threadIdx.x, n0 = blockIdx.x * 256;
    load_tiles<false>(sIn, sWt, X, H, W, n0, n, t);
    __syncthreads();
    int warp = t >> 5, lane = t & 31;
    int rg = warp >> 1, cg = warp & 1, lr = lane >> 2, lc = lane & 3;
    float acc[2][8][4];
#pragma unroll
    for (int mt = 0; mt < 2; mt++)
#pragma unroll
        for (int g = 0; g < 8; g++)
#pragma unroll
            for (int j = 0; j < 4; j++) acc[mt][g][j] = 0.f;
    mma_main(sIn, sWt, rg, cg, lr, lc, acc);
#pragma unroll
    for (int mt = 0; mt < 2; mt++) {
        int r0 = n0 + rg * 32 + mt * 16 + lr;
        int r1 = r0 + 8;
        float d0 = (r0 < n) ? g_dinv[r0] : 0.f;
        float d1 = (r1 < n) ? g_dinv[r1] : 0.f;
#pragma unroll
        for (int g = 0; g < 8; g++) {
            int col = cg * 64 + g * 8 + 2 * lc;
            if (r0 < n)
                *(__half2*)&out[(size_t)r0 * HID + col] =
                    __floats2half2_rn(acc[mt][g][0] * d0, acc[mt][g][1] * d0);
            if (r1 < n)
                *(__half2*)&out[(size_t)r1 * HID + col] =
                    __floats2half2_rn(acc[mt][g][2] * d1, acc[mt][g][3] * d1);
        }
    }
}

// fused f4+f5: out = sigmoid([x | relu([x|h]@W4+b4)] @ w5 + b5)
__global__ void __launch_bounds__(512, 1)
f45_tf32_kernel(const float* __restrict__ X, const __half* __restrict__ Hin,
                const float* __restrict__ W, const float* __restrict__ b4,
                const float* __restrict__ w5, const float* __restrict__ b5,
                float* __restrict__ out, int n) {
    extern __shared__ float sm[];
    float* sIn = sm;
    float* sWt = sm + 256 * KPAD;
    float* sPart = sWt + 128 * KPAD;     // [256][2]
    int t = threadIdx.x, n0 = blockIdx.x * 256;
    load_tiles<true>(sIn, sWt, X, Hin, W, n0, n, t);
    __syncthreads();
    int warp = t >> 5, lane = t & 31;
    int rg = warp >> 1, cg = warp & 1, lr = lane >> 2, lc = lane & 3;
    float acc[2][8][4];
#pragma unroll
    for (int mt = 0; mt < 2; mt++)
#pragma unroll
        for (int g = 0; g < 8; g++)
#pragma unroll
            for (int j = 0; j < 4; j++) acc[mt][g][j] = 0.f;
    mma_main(sIn, sWt, rg, cg, lr, lc, acc);

    float b4l[8][2], w5l[8][2];
#pragma unroll
    for (int g = 0; g < 8; g++) {
        int col = cg * 64 + g * 8 + 2 * lc;
        b4l[g][0] = b4[col];         b4l[g][1] = b4[col + 1];
        w5l[g][0] = w5[NFT + col];   w5l[g][1] = w5[NFT + col + 1];
    }
#pragma unroll
    for (int mt = 0; mt < 2; mt++)
#pragma unroll
        for (int h = 0; h < 2; h++) {
            float p = 0.f;
#pragma unroll
            for (int g = 0; g < 8; g++) {
                p = fmaf(fmaxf(acc[mt][g][2 * h] + b4l[g][0], 0.f), w5l[g][0], p);
                p = fmaf(fmaxf(acc[mt][g][2 * h + 1] + b4l[g][1], 0.f), w5l[g][1], p);
            }
            p += __shfl_xor_sync(0xffffffffu, p, 1);
            p += __shfl_xor_sync(0xffffffffu, p, 2);
            if (lc == 0) {
                int rl = rg * 32 + mt * 16 + h * 8 + lr;
                sPart[rl * 2 + cg] = p;
            }
        }
    __syncthreads();
    if (t < 256) {
        int node = n0 + t;
        if (node < n) {
            float s = sPart[t * 2] + sPart[t * 2 + 1] + b5[0];
#pragma unroll
            for (int k = 0; k < NFT; k++) s = fmaf(sIn[t * KPAD + k], w5[k], s);
            out[node] = 1.f / (1.f + expf(-s));
        }
    }
}

// ---------------- launch ----------------------------------------------------
extern "C" void kernel_launch(void* const* d_in, const int* in_sizes, int n_in,
                              void* d_out, int out_size) {
    const float* x   = (const float*)d_in[0];
    const int*   ew  = (const int*)d_in[1];
    const float* c1W = (const float*)d_in[2];
    const float* c1b = (const float*)d_in[3];
    const float* c2W = (const float*)d_in[4];
    const float* c2b = (const float*)d_in[5];
    const float* f4W = (const float*)d_in[18];
    const float* f4b = (const float*)d_in[19];
    const float* f5W = (const float*)d_in[20];
    const float* f5b = (const float*)d_in[21];
    float* out = (float*)d_out;

    const int n = in_sizes[0] / NFT;
    long ewn = in_sizes[1];
    int E = (int)(ewn / 2);
    if (E > MAXE) E = (int)(ewn / 4);

    __half *yw, *h;
    cudaGetSymbolAddress((void**)&yw, g_yw);
    cudaGetSymbolAddress((void**)&h, g_h);

    const int SM_MM  = (256 * KPAD + 128 * KPAD) * 4;        // 210432 B
    const int SM_F45 = SM_MM + 256 * 2 * 4;                  // 212480 B
    cudaFuncSetAttribute(mm2_tf32_kernel,
                         cudaFuncAttributeMaxDynamicSharedMemorySize, SM_MM);
    cudaFuncSetAttribute(f45_tf32_kernel,
                         cudaFuncAttributeMaxDynamicSharedMemorySize, SM_F45);

    const int eb256   = (E + 255) / 256;
    const int nb1024  = (n + 1023) / 1024;
    const int mm1b    = (n + 63) / 64;
    const int mmb     = (n + 255) / 256;
    const int gatherb = (n + 7) / 8;     // 8 warps (nodes) per 256-thread block

    // graph build (g_deg all-zero on entry: BSS init + scan_fin self-zero)
    hist_kernel<<<eb256, 256>>>(ew, E);            // #1 (inline dtype detect)
    scan_part_kernel<<<nb1024, 256>>>(n);          // #2
    scan_fin_kernel<<<nb1024, 256>>>(nb1024, n);   // #3 (inline top scan)
    fill_kernel<<<eb256, 256>>>(ew, E);            // #4  <- ncu capture slot

    // layer 1: yw1 = dinv*(x @ c1W) [fp16]; h1 = relu(dinv*(self+sum)+c1b)
    mm1_kernel<<<mm1b, 256>>>(x, c1W, yw, n);      // #5
    gather_kernel<<<gatherb, 256>>>(yw, c1b, h, n);// #6

    // layer 2: yw2 = dinv*([h1|x] @ c2W) [tf32 mma]; h2 = relu(...)
    mm2_tf32_kernel<<<mmb, 512, SM_MM>>>(x, h, c2W, yw, n);   // #7
    gather_kernel<<<gatherb, 256>>>(yw, c2b, h, n);           // #8

    // fused head: out = sigmoid([x | relu([x|h2]@f4W+f4b)] @ f5W + f5b)
    f45_tf32_kernel<<<mmb, 512, SM_F45>>>(x, h, f4W, f4b, f5W, f5b, out, n); // #9
}

// round 7
// speedup vs baseline: 1.6350x; 1.1375x over previous
#include <cuda_runtime.h>
#include <cuda_fp16.h>
#include <math.h>
#include <stdint.h>

// Problem constants (fixed shapes)
#define NN   100000
#define MAXE 1600000
#define HID  128
#define NFT  8
#define KTOT 136          // HID + NFT
#define KMMA 144          // padded to 9 chunks of 16
#define KPH  152          // smem row stride in halves (conflict-free: 76 words)

// ---------------- static device scratch (zero-initialized at load) ----------
__device__ int    g_deg[NN];        // invariant: all-zero at kernel_launch entry
__device__ int    g_off[NN + 1];
__device__ int    g_pos[NN];
__device__ float  g_dinv[NN];
__device__ int    g_srcs[MAXE];
__device__ int    g_part[512];
__device__ __half g_yw[(size_t)NN * HID];   // fp16 messages (25.6MB)
__device__ __half g_h[(size_t)NN * HID];    // fp16 hidden   (25.6MB)
__device__ int    g_is64;

// ---------------- hist (+inline int64/int32 detection) ----------------------
__global__ void hist_kernel(const int* __restrict__ ew, int E) {
    __shared__ int s_bad;
    if (threadIdx.x == 0) s_bad = 0;
    __syncthreads();
    if (threadIdx.x < 128 && ew[2 * threadIdx.x + 1] != 0) atomicOr(&s_bad, 1);
    __syncthreads();
    int is64 = s_bad ? 0 : 1;
    if (blockIdx.x == 0 && threadIdx.x == 0) g_is64 = is64;   // for fill
    int e = blockIdx.x * blockDim.x + threadIdx.x;
    if (e >= E) return;
    int d;
    if (is64) { int4 v = ((const int4*)ew)[e]; d = v.z; }
    else      { int2 v = ((const int2*)ew)[e]; d = v.y; }
    atomicAdd(&g_deg[d], 1);
}

// ---------------- hierarchical scan (1024 elems / 256-thread block) ---------
__device__ __forceinline__ int block_scan_excl(int v, int t, int* tot) {
    int lane = t & 31, wid = t >> 5;
    int x = v;
#pragma unroll
    for (int o = 1; o < 32; o <<= 1) {
        int y = __shfl_up_sync(0xffffffffu, x, o);
        if (lane >= o) x += y;
    }
    __shared__ int wsum[8];
    if (lane == 31) wsum[wid] = x;
    __syncthreads();
    int add = 0, total = 0;
#pragma unroll
    for (int w = 0; w < 8; w++) {
        if (w < wid) add += wsum[w];
        total += wsum[w];
    }
    *tot = total;
    __syncthreads();
    return add + x - v;   // exclusive prefix within block
}

__global__ void scan_part_kernel(int n) {
    int t = threadIdx.x, b = blockIdx.x;
    int base = b * 1024 + t * 4;
    int s = 0;
#pragma unroll
    for (int i = 0; i < 4; i++) {
        int idx = base + i;
        if (idx < n) s += g_deg[idx];
    }
    int tot;
    block_scan_excl(s, t, &tot);
    if (t == 0) g_part[b] = tot;
}

// scan_fin: inline top scan + per-element scan + pos/dinv init + deg self-zero
__global__ void scan_fin_kernel(int nb, int n) {
    __shared__ int sTop[256];
    int t = threadIdx.x, b = blockIdx.x;
    {
        int v = (t < nb) ? g_part[t] : 0;
        int tot;
        int e = block_scan_excl(v, t, &tot);
        sTop[t] = e;
        if (b == 0 && t == 0) g_off[n] = tot;
    }
    __syncthreads();
    int base = b * 1024 + t * 4;
    int d[4];
    int s = 0;
#pragma unroll
    for (int i = 0; i < 4; i++) {
        int idx = base + i;
        d[i] = (idx < n) ? g_deg[idx] : 0;
        s += d[i];
    }
    int tot;
    int e = block_scan_excl(s, t, &tot);
    int run = sTop[b] + e;
#pragma unroll
    for (int i = 0; i < 4; i++) {
        int idx = base + i;
        if (idx < n) {
            g_off[idx] = run;
            g_pos[idx] = run;
            g_dinv[idx] = rsqrtf((float)(d[i] + 1));   // +1 self-loop
            g_deg[idx] = 0;                            // restore invariant
            run += d[i];
        }
    }
}

__global__ void fill_kernel(const int* __restrict__ ew, int E) {
    int e = blockIdx.x * blockDim.x + threadIdx.x;
    if (e >= E) return;
    int s, d;
    if (g_is64) { int4 v = ((const int4*)ew)[e]; s = v.x; d = v.z; }
    else        { int2 v = ((const int2*)ew)[e]; s = v.x; d = v.y; }
    int idx = atomicAdd(&g_pos[d], 1);
    g_srcs[idx] = s;
}

// ---------------- layer-1 matmul (K=8, scalar), fp16 out --------------------
__global__ void mm1_kernel(const float* __restrict__ X, const float* __restrict__ W,
                           __half* __restrict__ out, int n) {
    __shared__ float sW[NFT * HID];
    __shared__ float sIn[64][NFT];
    int t = threadIdx.x, n0 = blockIdx.x * 64;
    for (int i = t; i < NFT * HID; i += 256) sW[i] = W[i];
    for (int i = t; i < 64 * NFT; i += 256) {
        int r = i >> 3, c = i & 7;
        int node = n0 + r;
        sIn[r][c] = (node < n) ? X[(size_t)node * NFT + c] : 0.f;
    }
    __syncthreads();
    int og = t & 15, ng = t >> 4;
    float acc[4][8];
#pragma unroll
    for (int i = 0; i < 4; i++)
#pragma unroll
        for (int j = 0; j < 8; j++) acc[i][j] = 0.f;
    const float4* sW4 = (const float4*)sW;
#pragma unroll
    for (int k = 0; k < NFT; k++) {
        float4 w0 = sW4[k * 32 + og * 2];
        float4 w1 = sW4[k * 32 + og * 2 + 1];
#pragma unroll
        for (int i = 0; i < 4; i++) {
            float a = sIn[ng * 4 + i][k];
            acc[i][0] = fmaf(a, w0.x, acc[i][0]);
            acc[i][1] = fmaf(a, w0.y, acc[i][1]);
            acc[i][2] = fmaf(a, w0.z, acc[i][2]);
            acc[i][3] = fmaf(a, w0.w, acc[i][3]);
            acc[i][4] = fmaf(a, w1.x, acc[i][4]);
            acc[i][5] = fmaf(a, w1.y, acc[i][5]);
            acc[i][6] = fmaf(a, w1.z, acc[i][6]);
            acc[i][7] = fmaf(a, w1.w, acc[i][7]);
        }
    }
#pragma unroll
    for (int i = 0; i < 4; i++) {
        int node = n0 + ng * 4 + i;
        if (node < n) {
            float di = g_dinv[node];
            __half2* o = (__half2*)&out[(size_t)node * HID + og * 8];
            o[0] = __floats2half2_rn(acc[i][0] * di, acc[i][1] * di);
            o[1] = __floats2half2_rn(acc[i][2] * di, acc[i][3] * di);
            o[2] = __floats2half2_rn(acc[i][4] * di, acc[i][5] * di);
            o[3] = __floats2half2_rn(acc[i][6] * di, acc[i][7] * di);
        }
    }
}

// ---------------- gather: warp/node, 2 edges/iter, fp32 accum, unroll 8 -----
__global__ void gather_kernel(const __half* __restrict__ yw,
                              const float* __restrict__ bias,
                              __half* __restrict__ out, int n) {
    int gw = (blockIdx.x * blockDim.x + threadIdx.x) >> 5;
    if (gw >= n) return;                    // uniform per warp
    int lane = threadIdx.x & 31;
    int hh = lane >> 4;                     // which edge of the pair
    int fl = lane & 15;                     // 16B feature chunk (8 halves)
    const uint4* yw4 = (const uint4*)yw;    // 16 uint4 per 128-half row

    float acc[8];
#pragma unroll
    for (int j = 0; j < 8; j++) acc[j] = 0.f;

    // self-loop term (counted once, by half 0)
    if (hh == 0) {
        uint4 v = yw4[(size_t)gw * 16 + fl];
        float2 a = __half22float2(*(__half2*)&v.x);
        float2 b = __half22float2(*(__half2*)&v.y);
        float2 c = __half22float2(*(__half2*)&v.z);
        float2 d = __half22float2(*(__half2*)&v.w);
        acc[0] = a.x; acc[1] = a.y; acc[2] = b.x; acc[3] = b.y;
        acc[4] = c.x; acc[5] = c.y; acc[6] = d.x; acc[7] = d.y;
    }

    int beg = g_off[gw], end = g_off[gw + 1];
    for (int base = beg; base < end; base += 32) {
        int idx = base + lane;
        int sreg = (idx < end) ? g_srcs[idx] : 0;
        int m = min(32, end - base);
#pragma unroll 8
        for (int i2 = 0; i2 < m; i2 += 2) {
            int e = i2 + hh;                              // e <= 31 always
            int s = __shfl_sync(0xffffffffu, sreg, e);
            if (e < m) {
                uint4 v = __ldg(&yw4[(size_t)s * 16 + fl]);
                float2 a = __half22float2(*(__half2*)&v.x);
                float2 b = __half22float2(*(__half2*)&v.y);
                float2 c = __half22float2(*(__half2*)&v.z);
                float2 d = __half22float2(*(__half2*)&v.w);
                acc[0] += a.x; acc[1] += a.y; acc[2] += b.x; acc[3] += b.y;
                acc[4] += c.x; acc[5] += c.y; acc[6] += d.x; acc[7] += d.y;
            }
        }
    }

    // combine the two edge-halves (lane l <-> l+16 hold same features)
#pragma unroll
    for (int j = 0; j < 8; j++)
        acc[j] += __shfl_xor_sync(0xffffffffu, acc[j], 16);

    if (hh == 0) {
        float di = g_dinv[gw];
        const float4* b4 = (const float4*)bias;
        float4 ba = b4[fl * 2], bb = b4[fl * 2 + 1];
        float r0 = fmaxf(fmaf(di, acc[0], ba.x), 0.f);
        float r1 = fmaxf(fmaf(di, acc[1], ba.y), 0.f);
        float r2 = fmaxf(fmaf(di, acc[2], ba.z), 0.f);
        float r3 = fmaxf(fmaf(di, acc[3], ba.w), 0.f);
        float r4 = fmaxf(fmaf(di, acc[4], bb.x), 0.f);
        float r5 = fmaxf(fmaf(di, acc[5], bb.y), 0.f);
        float r6 = fmaxf(fmaf(di, acc[6], bb.z), 0.f);
        float r7 = fmaxf(fmaf(di, acc[7], bb.w), 0.f);
        uint4 o;
        *(__half2*)&o.x = __floats2half2_rn(r0, r1);
        *(__half2*)&o.y = __floats2half2_rn(r2, r3);
        *(__half2*)&o.z = __floats2half2_rn(r4, r5);
        *(__half2*)&o.w = __floats2half2_rn(r6, r7);
        ((uint4*)out)[(size_t)gw * 16 + fl] = o;
    }
}

// ---------------- fp16 HMMA machinery (m16n8k16, fp32 accum) ----------------
__device__ __forceinline__ void mma_f16(float* c, const uint32_t* a, const uint32_t* b) {
    asm volatile(
        "mma.sync.aligned.m16n8k16.row.col.f32.f16.f16.f32 "
        "{%0,%1,%2,%3},{%4,%5,%6,%7},{%8,%9},{%0,%1,%2,%3};"
        : "+f"(c[0]), "+f"(c[1]), "+f"(c[2]), "+f"(c[3])
        : "r"(a[0]), "r"(a[1]), "r"(a[2]), "r"(a[3]), "r"(b[0]), "r"(b[1]));
}

// sIn[256][KPH] halves = concat + zero pad; sWt[col][KPH] halves = W^T.
// H rows copied as raw uint4 (already fp16). 512 threads.
// XFIRST: input = [X(8) | H(128) | pad8]; else [H(128) | X(8) | pad8].
template <bool XFIRST>
__device__ __forceinline__ void load_tiles_h(__half* sIn, __half* sWt,
                                             const float* __restrict__ X,
                                             const __half* __restrict__ H,
                                             const float* __restrict__ W,
                                             int n0, int n, int t) {
    int warp = t >> 5, lane = t & 31;
    const int hbase = XFIRST ? NFT : 0;
    const int xbase = XFIRST ? 0 : HID;
    for (int r = warp; r < 256; r += 16) {
        int node = n0 + r;
        bool ok = node < n;
        if (lane < 16) {
            uint4 v = make_uint4(0u, 0u, 0u, 0u);
            if (ok) v = __ldg(((const uint4*)(H + (size_t)node * HID)) + lane);
            *(uint4*)&sIn[r * KPH + hbase + lane * 8] = v;
        } else if (lane < 24) {
            int c = lane - 16;
            float xv = ok ? X[(size_t)node * NFT + c] : 0.f;
            sIn[r * KPH + xbase + c] = __float2half(xv);
        } else {
            int c = KTOT + (lane - 24);     // zero pad cols 136..143
            sIn[r * KPH + c] = __ushort_as_half((unsigned short)0);
        }
    }
    // W row-major [KTOT][128] -> sWt[col][k], k padded to KMMA with zeros
    for (int i = t; i < KMMA * HID; i += 512) {
        int k = i >> 7, c = i & 127;
        float wv = (k < KTOT) ? W[k * HID + c] : 0.f;
        sWt[c * KPH + k] = __float2half(wv);
    }
}

// Per-warp mainloop: 32 rows x 64 cols, K=144 in 9 chunks of 16.
__device__ __forceinline__ void mma_main_h(const __half* sIn, const __half* sWt,
                                           int rg, int cg, int gid, int tid,
                                           float acc[2][8][4]) {
#pragma unroll
    for (int kc = 0; kc < 9; kc++) {
        int k0 = kc * 16;
        uint32_t bfr[8][2];
#pragma unroll
        for (int g = 0; g < 8; g++) {
            int col = cg * 64 + g * 8 + gid;
            bfr[g][0] = *(const uint32_t*)&sWt[col * KPH + k0 + 2 * tid];
            bfr[g][1] = *(const uint32_t*)&sWt[col * KPH + k0 + 8 + 2 * tid];
        }
        uint32_t afr[2][4];
#pragma unroll
        for (int mt = 0; mt < 2; mt++) {
            int row = rg * 32 + mt * 16;
            afr[mt][0] = *(const uint32_t*)&sIn[(row + gid) * KPH + k0 + 2 * tid];
            afr[mt][1] = *(const uint32_t*)&sIn[(row + 8 + gid) * KPH + k0 + 2 * tid];
            afr[mt][2] = *(const uint32_t*)&sIn[(row + gid) * KPH + k0 + 8 + 2 * tid];
            afr[mt][3] = *(const uint32_t*)&sIn[(row + 8 + gid) * KPH + k0 + 8 + 2 * tid];
        }
#pragma unroll
        for (int mt = 0; mt < 2; mt++)
#pragma unroll
            for (int g = 0; g < 8; g++)
                mma_f16(acc[mt][g], afr[mt], bfr[g]);
    }
}

// yw = dinv * ([H|X] @ W), fp16 out. Tile 256 rows x 128 cols, 512 threads.
__global__ void __launch_bounds__(512, 1)
mm2_f16_kernel(const float* __restrict__ X, const __half* __restrict__ H,
               const float* __restrict__ W, __half* __restrict__ out, int n) {
    extern __shared__ __half smh[];
    __half* sIn = smh;
    __half* sWt = smh + 256 * KPH;
    int t = threadIdx.x, n0 = blockIdx.x * 256;
    load_tiles_h<false>(sIn, sWt, X, H, W, n0, n, t);
    __syncthreads();
    int warp = t >> 5, lane = t & 31;
    int rg = warp >> 1, cg = warp & 1, gid = lane >> 2, tid = lane & 3;
    float acc[2][8][4];
#pragma unroll
    for (int mt = 0; mt < 2; mt++)
#pragma unroll
        for (int g = 0; g < 8; g++)
#pragma unroll
            for (int j = 0; j < 4; j++) acc[mt][g][j] = 0.f;
    mma_main_h(sIn, sWt, rg, cg, gid, tid, acc);
#pragma unroll
    for (int mt = 0; mt < 2; mt++) {
        int r0 = n0 + rg * 32 + mt * 16 + gid;
        int r1 = r0 + 8;
        float d0 = (r0 < n) ? g_dinv[r0] : 0.f;
        float d1 = (r1 < n) ? g_dinv[r1] : 0.f;
#pragma unroll
        for (int g = 0; g < 8; g++) {
            int col = cg * 64 + g * 8 + 2 * tid;
            if (r0 < n)
                *(__half2*)&out[(size_t)r0 * HID + col] =
                    __floats2half2_rn(acc[mt][g][0] * d0, acc[mt][g][1] * d0);
            if (r1 < n)
                *(__half2*)&out[(size_t)r1 * HID + col] =
                    __floats2half2_rn(acc[mt][g][2] * d1, acc[mt][g][3] * d1);
        }
    }
}

// fused f4+f5: out = sigmoid([x | relu([x|h]@W4+b4)] @ w5 + b5)
__global__ void __launch_bounds__(512, 1)
f45_f16_kernel(const float* __restrict__ X, const __half* __restrict__ Hin,
               const float* __restrict__ W, const float* __restrict__ b4,
               const float* __restrict__ w5, const float* __restrict__ b5,
               float* __restrict__ out, int n) {
    extern __shared__ __half smh[];
    __half* sIn = smh;
    __half* sWt = smh + 256 * KPH;
    float* sPart = (float*)(smh + 256 * KPH + 128 * KPH);   // [256][2]
    int t = threadIdx.x, n0 = blockIdx.x * 256;
    load_tiles_h<true>(sIn, sWt, X, Hin, W, n0, n, t);
    __syncthreads();
    int warp = t >> 5, lane = t & 31;
    int rg = warp >> 1, cg = warp & 1, gid = lane >> 2, tid = lane & 3;
    float acc[2][8][4];
#pragma unroll
    for (int mt = 0; mt < 2; mt++)
#pragma unroll
        for (int g = 0; g < 8; g++)
#pragma unroll
            for (int j = 0; j < 4; j++) acc[mt][g][j] = 0.f;
    mma_main_h(sIn, sWt, rg, cg, gid, tid, acc);

    float b4l[8][2], w5l[8][2];
#pragma unroll
    for (int g = 0; g < 8; g++) {
        int col = cg * 64 + g * 8 + 2 * tid;
        b4l[g][0] = b4[col];         b4l[g][1] = b4[col + 1];
        w5l[g][0] = w5[NFT + col];   w5l[g][1] = w5[NFT + col + 1];
    }
#pragma unroll
    for (int mt = 0; mt < 2; mt++)
#pragma unroll
        for (int h = 0; h < 2; h++) {
            float p = 0.f;
#pragma unroll
            for (int g = 0; g < 8; g++) {
                p = fmaf(fmaxf(acc[mt][g][2 * h] + b4l[g][0], 0.f), w5l[g][0], p);
                p = fmaf(fmaxf(acc[mt][g][2 * h + 1] + b4l[g][1], 0.f), w5l[g][1], p);
            }
            p += __shfl_xor_sync(0xffffffffu, p, 1);
            p += __shfl_xor_sync(0xffffffffu, p, 2);
            if (tid == 0) {
                int rl = rg * 32 + mt * 16 + h * 8 + gid;
                sPart[rl * 2 + cg] = p;
            }
        }
    __syncthreads();
    if (t < 256) {
        int node = n0 + t;
        if (node < n) {
            float s = sPart[t * 2] + sPart[t * 2 + 1] + b5[0];
#pragma unroll
            for (int k = 0; k < NFT; k++)
                s = fmaf(__half2float(sIn[t * KPH + k]), w5[k], s);
            out[node] = 1.f / (1.f + expf(-s));
        }
    }
}

// ---------------- launch ----------------------------------------------------
extern "C" void kernel_launch(void* const* d_in, const int* in_sizes, int n_in,
                              void* d_out, int out_size) {
    const float* x   = (const float*)d_in[0];
    const int*   ew  = (const int*)d_in[1];
    const float* c1W = (const float*)d_in[2];
    const float* c1b = (const float*)d_in[3];
    const float* c2W = (const float*)d_in[4];
    const float* c2b = (const float*)d_in[5];
    const float* f4W = (const float*)d_in[18];
    const float* f4b = (const float*)d_in[19];
    const float* f5W = (const float*)d_in[20];
    const float* f5b = (const float*)d_in[21];
    float* out = (float*)d_out;

    const int n = in_sizes[0] / NFT;
    long ewn = in_sizes[1];
    int E = (int)(ewn / 2);
    if (E > MAXE) E = (int)(ewn / 4);

    __half *yw, *h;
    cudaGetSymbolAddress((void**)&yw, g_yw);
    cudaGetSymbolAddress((void**)&h, g_h);

    const int SM_MM  = (256 * KPH + 128 * KPH) * 2;          // 116736 B
    const int SM_F45 = SM_MM + 256 * 2 * 4;                  // 118784 B
    cudaFuncSetAttribute(mm2_f16_kernel,
                         cudaFuncAttributeMaxDynamicSharedMemorySize, SM_MM);
    cudaFuncSetAttribute(f45_f16_kernel,
                         cudaFuncAttributeMaxDynamicSharedMemorySize, SM_F45);

    const int eb256   = (E + 255) / 256;
    const int nb1024  = (n + 1023) / 1024;
    const int mm1b    = (n + 63) / 64;
    const int mmb     = (n + 255) / 256;
    const int gatherb = (n + 7) / 8;     // 8 warps (nodes) per 256-thread block

    // graph build (g_deg all-zero on entry: BSS init + scan_fin self-zero)
    hist_kernel<<<eb256, 256>>>(ew, E);            // #1 (inline dtype detect)
    scan_part_kernel<<<nb1024, 256>>>(n);          // #2
    scan_fin_kernel<<<nb1024, 256>>>(nb1024, n);   // #3 (inline top scan)
    fill_kernel<<<eb256, 256>>>(ew, E);            // #4  <- ncu capture slot

    // layer 1: yw1 = dinv*(x @ c1W) [fp16]; h1 = relu(dinv*(self+sum)+c1b)
    mm1_kernel<<<mm1b, 256>>>(x, c1W, yw, n);      // #5
    gather_kernel<<<gatherb, 256>>>(yw, c1b, h, n);// #6

    // layer 2: yw2 = dinv*([h1|x] @ c2W) [fp16 HMMA]; h2 = relu(...)
    mm2_f16_kernel<<<mmb, 512, SM_MM>>>(x, h, c2W, yw, n);    // #7
    gather_kernel<<<gatherb, 256>>>(yw, c2b, h, n);           // #8

    // fused head: out = sigmoid([x | relu([x|h2]@f4W+f4b)] @ f5W + f5b)
    f45_f16_kernel<<<mmb, 512, SM_F45>>>(x, h, f4W, f4b, f5W, f5b, out, n); // #9
}

// round 8
// speedup vs baseline: 1.7459x; 1.0678x over previous
#include <cuda_runtime.h>
#include <cuda_fp16.h>
#include <math.h>
#include <stdint.h>

// Problem constants (fixed shapes)
#define NN   100000
#define MAXE 1600000
#define HID  128
#define NFT  8
#define KTOT 136          // HID + NFT
#define KMMA 144          // padded to 9 chunks of 16
#define KPH  152          // smem row stride in halves (conflict-free)

// ---------------- static device scratch (zero-initialized at load) ----------
__device__ int    g_deg[NN];        // invariant: all-zero at kernel_launch entry
__device__ int    g_off[NN + 1];
__device__ int    g_pos[NN];
__device__ float  g_dinv[NN];
__device__ int    g_srcs[MAXE];
__device__ int    g_part[512];
__device__ float  g_xd[(size_t)NN * NFT];   // dinv_s * x_s   (3.2MB fp32)
__device__ float  g_u[(size_t)NN * NFT];    // dinv_d * z_d   (3.2MB fp32)
__device__ __half g_bufA[(size_t)NN * HID]; // h1d, later h2  (25.6MB fp16)
__device__ __half g_bufB[(size_t)NN * HID]; // wsc            (25.6MB fp16)
__device__ int    g_is64;

// ---------------- hist (+inline int64/int32 detection) ----------------------
__global__ void hist_kernel(const int* __restrict__ ew, int E) {
    __shared__ int s_bad;
    if (threadIdx.x == 0) s_bad = 0;
    __syncthreads();
    if (threadIdx.x < 128 && ew[2 * threadIdx.x + 1] != 0) atomicOr(&s_bad, 1);
    __syncthreads();
    int is64 = s_bad ? 0 : 1;
    if (blockIdx.x == 0 && threadIdx.x == 0) g_is64 = is64;   // for fill
    int e = blockIdx.x * blockDim.x + threadIdx.x;
    if (e >= E) return;
    int d;
    if (is64) { int4 v = ((const int4*)ew)[e]; d = v.z; }
    else      { int2 v = ((const int2*)ew)[e]; d = v.y; }
    atomicAdd(&g_deg[d], 1);
}

// ---------------- hierarchical scan (1024 elems / 256-thread block) ---------
__device__ __forceinline__ int block_scan_excl(int v, int t, int* tot) {
    int lane = t & 31, wid = t >> 5;
    int x = v;
#pragma unroll
    for (int o = 1; o < 32; o <<= 1) {
        int y = __shfl_up_sync(0xffffffffu, x, o);
        if (lane >= o) x += y;
    }
    __shared__ int wsum[8];
    if (lane == 31) wsum[wid] = x;
    __syncthreads();
    int add = 0, total = 0;
#pragma unroll
    for (int w = 0; w < 8; w++) {
        if (w < wid) add += wsum[w];
        total += wsum[w];
    }
    *tot = total;
    __syncthreads();
    return add + x - v;   // exclusive prefix within block
}

__global__ void scan_part_kernel(int n) {
    int t = threadIdx.x, b = blockIdx.x;
    int base = b * 1024 + t * 4;
    int s = 0;
#pragma unroll
    for (int i = 0; i < 4; i++) {
        int idx = base + i;
        if (idx < n) s += g_deg[idx];
    }
    int tot;
    block_scan_excl(s, t, &tot);
    if (t == 0) g_part[b] = tot;
}

// scan_fin: inline top scan + per-element scan + pos/dinv init + deg self-zero
// + xd = dinv * x precompute (for the 8-dim gather).
__global__ void scan_fin_kernel(int nb, int n, const float* __restrict__ X) {
    __shared__ int sTop[256];
    int t = threadIdx.x, b = blockIdx.x;
    {
        int v = (t < nb) ? g_part[t] : 0;
        int tot;
        int e = block_scan_excl(v, t, &tot);
        sTop[t] = e;
        if (b == 0 && t == 0) g_off[n] = tot;
    }
    __syncthreads();
    int base = b * 1024 + t * 4;
    int d[4];
    int s = 0;
#pragma unroll
    for (int i = 0; i < 4; i++) {
        int idx = base + i;
        d[i] = (idx < n) ? g_deg[idx] : 0;
        s += d[i];
    }
    int tot;
    int e = block_scan_excl(s, t, &tot);
    int run = sTop[b] + e;
#pragma unroll
    for (int i = 0; i < 4; i++) {
        int idx = base + i;
        if (idx < n) {
            g_off[idx] = run;
            g_pos[idx] = run;
            float di = rsqrtf((float)(d[i] + 1));   // +1 self-loop
            g_dinv[idx] = di;
            g_deg[idx] = 0;                         // restore invariant
            float4 xa = ((const float4*)X)[idx * 2];
            float4 xb = ((const float4*)X)[idx * 2 + 1];
            float4* o = (float4*)&g_xd[(size_t)idx * NFT];
            o[0] = make_float4(xa.x * di, xa.y * di, xa.z * di, xa.w * di);
            o[1] = make_float4(xb.x * di, xb.y * di, xb.z * di, xb.w * di);
            run += d[i];
        }
    }
}

__global__ void fill_kernel(const int* __restrict__ ew, int E) {
    int e = blockIdx.x * blockDim.x + threadIdx.x;
    if (e >= E) return;
    int s, d;
    if (g_is64) { int4 v = ((const int4*)ew)[e]; s = v.x; d = v.z; }
    else        { int2 v = ((const int2*)ew)[e]; s = v.x; d = v.y; }
    int idx = atomicAdd(&g_pos[d], 1);
    g_srcs[idx] = s;
}

// ---------------- gatherX: 8-dim fp32 gather (32B = 1 sector per edge) ------
// u[d] = dinv_d * ( xd[d] + sum_{s in N(d)} xd[s] ),  xd = dinv*x.
// Warp per node; 4 edges per iteration (8 lanes each), unroll 8.
__global__ void gatherx_kernel(float* __restrict__ u, int n) {
    int gw = (blockIdx.x * blockDim.x + threadIdx.x) >> 5;
    if (gw >= n) return;
    int lane = threadIdx.x & 31;
    int q  = lane >> 3;      // quarter = which edge of the 4
    int fl = lane & 7;       // feature index
    float acc = 0.f;
    int beg = g_off[gw], end = g_off[gw + 1];
    for (int base = beg; base < end; base += 32) {
        int idx = base + lane;
        int sreg = (idx < end) ? g_srcs[idx] : 0;
        int m = min(32, end - base);
#pragma unroll 8
        for (int i4 = 0; i4 < m; i4 += 4) {
            int e = i4 + q;                           // e <= 31 always
            int s = __shfl_sync(0xffffffffu, sreg, e);
            if (e < m) acc += __ldg(&g_xd[(size_t)s * NFT + fl]);
        }
    }
    acc += __shfl_xor_sync(0xffffffffu, acc, 8);
    acc += __shfl_xor_sync(0xffffffffu, acc, 16);
    if (lane < 8) {
        float z = acc + g_xd[(size_t)gw * NFT + fl];  // self term
        u[(size_t)gw * NFT + fl] = g_dinv[gw] * z;
    }
}

// ---------------- mm_h1: h1d = dinv * relu(u @ c1W + b1), fp16 out ----------
__global__ void mmh1_kernel(const float* __restrict__ U, const float* __restrict__ W,
                            const float* __restrict__ B, __half* __restrict__ out,
                            int n) {
    __shared__ float sW[NFT * HID];
    __shared__ float sIn[64][NFT];
    int t = threadIdx.x, n0 = blockIdx.x * 64;
    for (int i = t; i < NFT * HID; i += 256) sW[i] = W[i];
    for (int i = t; i < 64 * NFT; i += 256) {
        int r = i >> 3, c = i & 7;
        int node = n0 + r;
        sIn[r][c] = (node < n) ? U[(size_t)node * NFT + c] : 0.f;
    }
    __syncthreads();
    int og = t & 15, ng = t >> 4;
    float acc[4][8];
#pragma unroll
    for (int i = 0; i < 4; i++)
#pragma unroll
        for (int j = 0; j < 8; j++) acc[i][j] = 0.f;
    const float4* sW4 = (const float4*)sW;
#pragma unroll
    for (int k = 0; k < NFT; k++) {
        float4 w0 = sW4[k * 32 + og * 2];
        float4 w1 = sW4[k * 32 + og * 2 + 1];
#pragma unroll
        for (int i = 0; i < 4; i++) {
            float a = sIn[ng * 4 + i][k];
            acc[i][0] = fmaf(a, w0.x, acc[i][0]);
            acc[i][1] = fmaf(a, w0.y, acc[i][1]);
            acc[i][2] = fmaf(a, w0.z, acc[i][2]);
            acc[i][3] = fmaf(a, w0.w, acc[i][3]);
            acc[i][4] = fmaf(a, w1.x, acc[i][4]);
            acc[i][5] = fmaf(a, w1.y, acc[i][5]);
            acc[i][6] = fmaf(a, w1.z, acc[i][6]);
            acc[i][7] = fmaf(a, w1.w, acc[i][7]);
        }
    }
    float bl[8];
#pragma unroll
    for (int j = 0; j < 8; j++) bl[j] = B[og * 8 + j];
#pragma unroll
    for (int i = 0; i < 4; i++) {
        int node = n0 + ng * 4 + i;
        if (node < n) {
            float di = g_dinv[node];
            __half2* o = (__half2*)&out[(size_t)node * HID + og * 8];
#pragma unroll
            for (int j = 0; j < 4; j++) {
                float v0 = fmaxf(acc[i][2 * j]     + bl[2 * j],     0.f) * di;
                float v1 = fmaxf(acc[i][2 * j + 1] + bl[2 * j + 1], 0.f) * di;
                o[j] = __floats2half2_rn(v0, v1);
            }
        }
    }
}

// ---------------- gatherW: wsc[d] = dinv_d * sum_{s in N+self} h1d[s] -------
// fp16 rows (256B/edge), fp32 accum, warp/node, 2 edges/iter, unroll 8.
__global__ void gatherw_kernel(const __half* __restrict__ hd,
                               __half* __restrict__ out, int n) {
    int gw = (blockIdx.x * blockDim.x + threadIdx.x) >> 5;
    if (gw >= n) return;
    int lane = threadIdx.x & 31;
    int hh = lane >> 4;
    int fl = lane & 15;
    const uint4* hd4 = (const uint4*)hd;

    float acc[8];
#pragma unroll
    for (int j = 0; j < 8; j++) acc[j] = 0.f;

    if (hh == 0) {                      // self term counted once
        uint4 v = hd4[(size_t)gw * 16 + fl];
        float2 a = __half22float2(*(__half2*)&v.x);
        float2 b = __half22float2(*(__half2*)&v.y);
        float2 c = __half22float2(*(__half2*)&v.z);
        float2 d = __half22float2(*(__half2*)&v.w);
        acc[0] = a.x; acc[1] = a.y; acc[2] = b.x; acc[3] = b.y;
        acc[4] = c.x; acc[5] = c.y; acc[6] = d.x; acc[7] = d.y;
    }

    int beg = g_off[gw], end = g_off[gw + 1];
    for (int base = beg; base < end; base += 32) {
        int idx = base + lane;
        int sreg = (idx < end) ? g_srcs[idx] : 0;
        int m = min(32, end - base);
#pragma unroll 8
        for (int i2 = 0; i2 < m; i2 += 2) {
            int e = i2 + hh;
            int s = __shfl_sync(0xffffffffu, sreg, e);
            if (e < m) {
                uint4 v = __ldg(&hd4[(size_t)s * 16 + fl]);
                float2 a = __half22float2(*(__half2*)&v.x);
                float2 b = __half22float2(*(__half2*)&v.y);
                float2 c = __half22float2(*(__half2*)&v.z);
                float2 d = __half22float2(*(__half2*)&v.w);
                acc[0] += a.x; acc[1] += a.y; acc[2] += b.x; acc[3] += b.y;
                acc[4] += c.x; acc[5] += c.y; acc[6] += d.x; acc[7] += d.y;
            }
        }
    }

#pragma unroll
    for (int j = 0; j < 8; j++)
        acc[j] += __shfl_xor_sync(0xffffffffu, acc[j], 16);

    if (hh == 0) {
        float di = g_dinv[gw];
        uint4 o;
        *(__half2*)&o.x = __floats2half2_rn(acc[0] * di, acc[1] * di);
        *(__half2*)&o.y = __floats2half2_rn(acc[2] * di, acc[3] * di);
        *(__half2*)&o.z = __floats2half2_rn(acc[4] * di, acc[5] * di);
        *(__half2*)&o.w = __floats2half2_rn(acc[6] * di, acc[7] * di);
        ((uint4*)out)[(size_t)gw * 16 + fl] = o;
    }
}

// ---------------- fp16 HMMA machinery (m16n8k16, fp32 accum) ----------------
__device__ __forceinline__ void mma_f16(float* c, const uint32_t* a, const uint32_t* b) {
    asm volatile(
        "mma.sync.aligned.m16n8k16.row.col.f32.f16.f16.f32 "
        "{%0,%1,%2,%3},{%4,%5,%6,%7},{%8,%9},{%0,%1,%2,%3};"
        : "+f"(c[0]), "+f"(c[1]), "+f"(c[2]), "+f"(c[3])
        : "r"(a[0]), "r"(a[1]), "r"(a[2]), "r"(a[3]), "r"(b[0]), "r"(b[1]));
}

// sIn[256][KPH] halves; sWt[col][KPH] halves = W^T. 512 threads.
// XFIRST: input = [U(8) | H(128) | pad]; else [H(128) | U(8) | pad].
// U is fp32 [n][8] (converted), H is fp16 [n][128] (raw uint4 copy).
template <bool XFIRST>
__device__ __forceinline__ void load_tiles_h(__half* sIn, __half* sWt,
                                             const float* __restrict__ U,
                                             const __half* __restrict__ H,
                                             const float* __restrict__ W,
                                             int n0, int n, int t) {
    int warp = t >> 5, lane = t & 31;
    const int hbase = XFIRST ? NFT : 0;
    const int xbase = XFIRST ? 0 : HID;
    for (int r = warp; r < 256; r += 16) {
        int node = n0 + r;
        bool ok = node < n;
        if (lane < 16) {
            uint4 v = make_uint4(0u, 0u, 0u, 0u);
            if (ok) v = __ldg(((const uint4*)(H + (size_t)node * HID)) + lane);
            *(uint4*)&sIn[r * KPH + hbase + lane * 8] = v;
        } else if (lane < 24) {
            int c = lane - 16;
            float xv = ok ? U[(size_t)node * NFT + c] : 0.f;
            sIn[r * KPH + xbase + c] = __float2half(xv);
        } else {
            int c = KTOT + (lane - 24);     // zero pad cols 136..143
            sIn[r * KPH + c] = __ushort_as_half((unsigned short)0);
        }
    }
    for (int i = t; i < KMMA * HID; i += 512) {
        int k = i >> 7, c = i & 127;
        float wv = (k < KTOT) ? W[k * HID + c] : 0.f;
        sWt[c * KPH + k] = __float2half(wv);
    }
}

// Per-warp mainloop: 32 rows x 64 cols, K=144 in 9 chunks of 16.
__device__ __forceinline__ void mma_main_h(const __half* sIn, const __half* sWt,
                                           int rg, int cg, int gid, int tid,
                                           float acc[2][8][4]) {
#pragma unroll
    for (int kc = 0; kc < 9; kc++) {
        int k0 = kc * 16;
        uint32_t bfr[8][2];
#pragma unroll
        for (int g = 0; g < 8; g++) {
            int col = cg * 64 + g * 8 + gid;
            bfr[g][0] = *(const uint32_t*)&sWt[col * KPH + k0 + 2 * tid];
            bfr[g][1] = *(const uint32_t*)&sWt[col * KPH + k0 + 8 + 2 * tid];
        }
        uint32_t afr[2][4];
#pragma unroll
        for (int mt = 0; mt < 2; mt++) {
            int row = rg * 32 + mt * 16;
            afr[mt][0] = *(const uint32_t*)&sIn[(row + gid) * KPH + k0 + 2 * tid];
            afr[mt][1] = *(const uint32_t*)&sIn[(row + 8 + gid) * KPH + k0 + 2 * tid];
            afr[mt][2] = *(const uint32_t*)&sIn[(row + gid) * KPH + k0 + 8 + 2 * tid];
            afr[mt][3] = *(const uint32_t*)&sIn[(row + 8 + gid) * KPH + k0 + 8 + 2 * tid];
        }
#pragma unroll
        for (int mt = 0; mt < 2; mt++)
#pragma unroll
            for (int g = 0; g < 8; g++)
                mma_f16(acc[mt][g], afr[mt], bfr[g]);
    }
}

// mm_h2: h2 = relu([wsc | u] @ c2W + b2), fp16 out. 256x128 tile, 512 threads.
__global__ void __launch_bounds__(512, 1)
mmh2_f16_kernel(const float* __restrict__ U, const __half* __restrict__ Wsc,
                const float* __restrict__ W, const float* __restrict__ B,
                __half* __restrict__ out, int n) {
    extern __shared__ __half smh[];
    __half* sIn = smh;
    __half* sWt = smh + 256 * KPH;
    int t = threadIdx.x, n0 = blockIdx.x * 256;
    load_tiles_h<false>(sIn, sWt, U, Wsc, W, n0, n, t);   // [wsc | u]
    __syncthreads();
    int warp = t >> 5, lane = t & 31;
    int rg = warp >> 1, cg = warp & 1, gid = lane >> 2, tid = lane & 3;
    float acc[2][8][4];
#pragma unroll
    for (int mt = 0; mt < 2; mt++)
#pragma unroll
        for (int g = 0; g < 8; g++)
#pragma unroll
            for (int j = 0; j < 4; j++) acc[mt][g][j] = 0.f;
    mma_main_h(sIn, sWt, rg, cg, gid, tid, acc);
#pragma unroll
    for (int mt = 0; mt < 2; mt++) {
        int r0 = n0 + rg * 32 + mt * 16 + gid;
        int r1 = r0 + 8;
#pragma unroll
        for (int g = 0; g < 8; g++) {
            int col = cg * 64 + g * 8 + 2 * tid;
            float b0 = B[col], b1 = B[col + 1];
            if (r0 < n)
                *(__half2*)&out[(size_t)r0 * HID + col] =
                    __floats2half2_rn(fmaxf(acc[mt][g][0] + b0, 0.f),
                                      fmaxf(acc[mt][g][1] + b1, 0.f));
            if (r1 < n)
                *(__half2*)&out[(size_t)r1 * HID + col] =
                    __floats2half2_rn(fmaxf(acc[mt][g][2] + b0, 0.f),
                                      fmaxf(acc[mt][g][3] + b1, 0.f));
        }
    }
}

// fused f4+f5: out = sigmoid([x | relu([x|h2]@W4+b4)] @ w5 + b5)
__global__ void __launch_bounds__(512, 1)
f45_f16_kernel(const float* __restrict__ X, const __half* __restrict__ Hin,
               const float* __restrict__ W, const float* __restrict__ b4,
               const float* __restrict__ w5, const float* __restrict__ b5,
               float* __restrict__ out, int n) {
    extern __shared__ __half smh[];
    __half* sIn = smh;
    __half* sWt = smh + 256 * KPH;
    float* sPart = (float*)(smh + 256 * KPH + 128 * KPH);   // [256][2]
    int t = threadIdx.x, n0 = blockIdx.x * 256;
    load_tiles_h<true>(sIn, sWt, X, Hin, W, n0, n, t);      // [x | h2]
    __syncthreads();
    int warp = t >> 5, lane = t & 31;
    int rg = warp >> 1, cg = warp & 1, gid = lane >> 2, tid = lane & 3;
    float acc[2][8][4];
#pragma unroll
    for (int mt = 0; mt < 2; mt++)
#pragma unroll
        for (int g = 0; g < 8; g++)
#pragma unroll
            for (int j = 0; j < 4; j++) acc[mt][g][j] = 0.f;
    mma_main_h(sIn, sWt, rg, cg, gid, tid, acc);

    float b4l[8][2], w5l[8][2];
#pragma unroll
    for (int g = 0; g < 8; g++) {
        int col = cg * 64 + g * 8 + 2 * tid;
        b4l[g][0] = b4[col];         b4l[g][1] = b4[col + 1];
        w5l[g][0] = w5[NFT + col];   w5l[g][1] = w5[NFT + col + 1];
    }
#pragma unroll
    for (int mt = 0; mt < 2; mt++)
#pragma unroll
        for (int h = 0; h < 2; h++) {
            float p = 0.f;
#pragma unroll
            for (int g = 0; g < 8; g++) {
                p = fmaf(fmaxf(acc[mt][g][2 * h] + b4l[g][0], 0.f), w5l[g][0], p);
                p = fmaf(fmaxf(acc[mt][g][2 * h + 1] + b4l[g][1], 0.f), w5l[g][1], p);
            }
            p += __shfl_xor_sync(0xffffffffu, p, 1);
            p += __shfl_xor_sync(0xffffffffu, p, 2);
            if (tid == 0) {
                int rl = rg * 32 + mt * 16 + h * 8 + gid;
                sPart[rl * 2 + cg] = p;
            }
        }
    __syncthreads();
    if (t < 256) {
        int node = n0 + t;
        if (node < n) {
            float s = sPart[t * 2] + sPart[t * 2 + 1] + b5[0];
#pragma unroll
            for (int k = 0; k < NFT; k++)
                s = fmaf(__half2float(sIn[t * KPH + k]), w5[k], s);
            out[node] = 1.f / (1.f + expf(-s));
        }
    }
}

// ---------------- launch ----------------------------------------------------
extern "C" void kernel_launch(void* const* d_in, const int* in_sizes, int n_in,
                              void* d_out, int out_size) {
    const float* x   = (const float*)d_in[0];
    const int*   ew  = (const int*)d_in[1];
    const float* c1W = (const float*)d_in[2];
    const float* c1b = (const float*)d_in[3];
    const float* c2W = (const float*)d_in[4];
    const float* c2b = (const float*)d_in[5];
    const float* f4W = (const float*)d_in[18];
    const float* f4b = (const float*)d_in[19];
    const float* f5W = (const float*)d_in[20];
    const float* f5b = (const float*)d_in[21];
    float* out = (float*)d_out;

    const int n = in_sizes[0] / NFT;
    long ewn = in_sizes[1];
    int E = (int)(ewn / 2);
    if (E > MAXE) E = (int)(ewn / 4);

    __half *bufA, *bufB; float* u;
    cudaGetSymbolAddress((void**)&bufA, g_bufA);
    cudaGetSymbolAddress((void**)&bufB, g_bufB);
    cudaGetSymbolAddress((void**)&u, g_u);

    const int SM_MM  = (256 * KPH + 128 * KPH) * 2;          // 116736 B
    const int SM_F45 = SM_MM + 256 * 2 * 4;                  // 118784 B
    cudaFuncSetAttribute(mmh2_f16_kernel,
                         cudaFuncAttributeMaxDynamicSharedMemorySize, SM_MM);
    cudaFuncSetAttribute(f45_f16_kernel,
                         cudaFuncAttributeMaxDynamicSharedMemorySize, SM_F45);

    const int eb256   = (E + 255) / 256;
    const int nb1024  = (n + 1023) / 1024;
    const int mm1b    = (n + 63) / 64;
    const int mmb     = (n + 255) / 256;
    const int gatherb = (n + 7) / 8;     // 8 warps (nodes) per 256-thread block

    // graph build (g_deg all-zero on entry: BSS init + scan_fin self-zero)
    hist_kernel<<<eb256, 256>>>(ew, E);               // #1 (inline dtype detect)
    scan_part_kernel<<<nb1024, 256>>>(n);             // #2
    scan_fin_kernel<<<nb1024, 256>>>(nb1024, n, x);   // #3 (+xd precompute)
    fill_kernel<<<eb256, 256>>>(ew, E);               // #4  <- ncu capture slot

    // layer 1 (aggregate-then-transform):
    // u = dinv*(xd[self]+sum xd[s]) [8-dim fp32 gather, 1 sector/edge]
    gatherx_kernel<<<gatherb, 256>>>(u, n);           // #5
    // h1d = dinv * relu(u @ c1W + c1b)  [fp16]
    mmh1_kernel<<<mm1b, 256>>>(u, c1W, c1b, bufA, n); // #6

    // layer 2: wsc = dinv * sum h1d[s]  [128-dim fp16 gather]
    gatherw_kernel<<<gatherb, 256>>>(bufA, bufB, n);  // #7
    // h2 = relu([wsc|u] @ c2W + c2b)  [fp16 HMMA]
    mmh2_f16_kernel<<<mmb, 512, SM_MM>>>(u, bufB, c2W, c2b, bufA, n); // #8

    // fused head: out = sigmoid([x | relu([x|h2]@f4W+f4b)] @ f5W + f5b)
    f45_f16_kernel<<<mmb, 512, SM_F45>>>(x, bufA, f4W, f4b, f5W, f5b,
                                         out, n);     // #9
}